// round 9
// baseline (speedup 1.0000x reference)
#include <cuda_runtime.h>
#include <cuda_bf16.h>

#define NN 8192
#define DIN 7
#define DH 8
#define DOUTK 23
#define KC 8                  /* K-chunks (grid.x), 1024 j each */
#define MT 64                 /* M-tiles of 128 i  (grid.y)     */
#define CJ 1024               /* j per chunk                    */
#define KSTEPS (CJ / 16)      /* 64 mma K-steps per chunk       */

// -------- device scratch (no allocations allowed) --------
__device__ float4 g_wv[NN * 2];              // per j fp32: {wv0..3},{wv4..6,w}
__device__ float g_cA[(NN / 2) * 4];         // per j-pair: {-x0a,-x0b,-x1a,-x1b}
__device__ float g_cB[(NN / 2) * 2];         // per j-pair: {-x2a,-x2b}
__device__ __nv_bfloat16 g_wvbf[16 * NN];    // rows 0-7 hi, 8-15 lo (K-major)
__device__ uint4 g_bfrag[KC * KSTEPS * 32];  // preassembled B fragments
__device__ float g_part[KC][NN][8];          // K-chunk partial accumulators

__device__ __forceinline__ float leaky(float v) {
    return v >= 0.0f ? v : 0.01f * v;
}

// one bf16x2 mask word: lanes of f32x2 = (j even, j odd)
// d = (|ci0-cj0| + |ci1-cj1|) + |ci2-cj2|  -- reference fp32 order, j pre-negated
#define MASKW(out, ci0, ci1, ci2, cj0, cj1, cj2)                          \
    asm("{\n\t"                                                           \
        ".reg .b64 u0,u1,u2,dd;\n\t"                                      \
        ".reg .b32 ea,eb,m0,m1;\n\t"                                      \
        ".reg .pred pa,pb;\n\t"                                           \
        "add.rn.f32x2 u0, %1, %4;\n\t"                                    \
        "add.rn.f32x2 u1, %2, %5;\n\t"                                    \
        "add.rn.f32x2 u2, %3, %6;\n\t"                                    \
        "and.b64 u0, u0, 0x7FFFFFFF7FFFFFFF;\n\t"                         \
        "and.b64 u1, u1, 0x7FFFFFFF7FFFFFFF;\n\t"                         \
        "and.b64 u2, u2, 0x7FFFFFFF7FFFFFFF;\n\t"                         \
        "add.rn.f32x2 dd, u0, u1;\n\t"                                    \
        "add.rn.f32x2 dd, dd, u2;\n\t"                                    \
        "mov.b64 {ea,eb}, dd;\n\t"                                        \
        "setp.le.u32 pa, ea, 0x40666666;\n\t"                             \
        "setp.le.u32 pb, eb, 0x40666666;\n\t"                             \
        "selp.b32 m0, 0x00003F80, 0, pa;\n\t"                             \
        "selp.b32 m1, 0x3F800000, 0, pb;\n\t"                             \
        "or.b32 %0, m0, m1;\n\t"                                          \
        "}"                                                               \
        : "=r"(out)                                                       \
        : "l"(ci0), "l"(ci1), "l"(ci2), "l"(cj0), "l"(cj1), "l"(cj2))

#define MMA_BF16(d0, d1, d2, d3, a0, a1, a2, a3, b0, b1)                  \
    asm("mma.sync.aligned.m16n8k16.row.col.f32.bf16.bf16.f32 "            \
        "{%0,%1,%2,%3}, {%4,%5,%6,%7}, {%8,%9}, {%0,%1,%2,%3};"           \
        : "+f"(d0), "+f"(d1), "+f"(d2), "+f"(d3)                          \
        : "r"(a0), "r"(a1), "r"(a2), "r"(a3), "r"(b0), "r"(b1))

// ---------------- Kernel A: per-node MLP + exp weights ----------------
__global__ void __launch_bounds__(32) prep_kernel(
    const float* __restrict__ x,
    const float* __restrict__ W1, const float* __restrict__ b1,
    const float* __restrict__ W2, const float* __restrict__ b2,
    const float* __restrict__ W3, const float* __restrict__ b3)
{
    __shared__ float sW1[DH * DIN], sb1[DH], sW2[DH * DH], sb2[DH],
                     sW3[DOUTK * DH], sb3[DOUTK];
    __shared__ float sx[32 * DIN];
    const int t = threadIdx.x;
    {
        const float* xb = x + blockIdx.x * 32 * DIN;
        for (int k = t; k < 32 * DIN; k += 32) sx[k] = xb[k];
        for (int k = t; k < DH * DIN; k += 32) sW1[k] = W1[k];
        for (int k = t; k < DH * DH; k += 32) sW2[k] = W2[k];
        for (int k = t; k < DOUTK * DH; k += 32) sW3[k] = W3[k];
        if (t < DH) { sb1[t] = b1[t]; sb2[t] = b2[t]; }
        if (t < DOUTK) sb3[t] = b3[t];
    }
    __syncthreads();

    const int j = blockIdx.x * 32 + t;

    float xv[DIN];
#pragma unroll
    for (int k = 0; k < DIN; k++) xv[k] = sx[t * DIN + k];

    float h1[DH];
#pragma unroll
    for (int c = 0; c < DH; c++) {
        float z = sb1[c];
#pragma unroll
        for (int k = 0; k < DIN; k++) z += sW1[c * DIN + k] * xv[k];
        h1[c] = leaky(z);
    }
    float h2[DH];
#pragma unroll
    for (int c = 0; c < DH; c++) {
        float z = sb2[c];
#pragma unroll
        for (int k = 0; k < DH; k++) z += sW2[c * DH + k] * h1[k];
        h2[c] = leaky(z);
    }
    float h3[DOUTK];
#pragma unroll
    for (int c = 0; c < DOUTK; c++) {
        float z = sb3[c];
#pragma unroll
        for (int k = 0; k < DH; k++) z += sW3[c * DH + k] * h2[k];
        h3[c] = z;   // layer 3 is linear
    }

    float s = 0.0f;
#pragma unroll
    for (int k = 0; k < 8; k++) s += h3[DIN + k] * h3[DIN + 8 + k];
    const float w = expf(s);

    g_wv[2 * j]     = make_float4(w * h3[0], w * h3[1], w * h3[2], w * h3[3]);
    g_wv[2 * j + 1] = make_float4(w * h3[4], w * h3[5], w * h3[6], w);

    // bf16 hi/lo split of the 8 aggregation channels (vals0..6, w)
#pragma unroll
    for (int c = 0; c < 8; c++) {
        const float v = (c < 7) ? w * h3[c] : w;
        const __nv_bfloat16 hi = __float2bfloat16(v);
        const __nv_bfloat16 lo = __float2bfloat16(v - __bfloat162float(hi));
        g_wvbf[c * NN + j] = hi;
        g_wvbf[(8 + c) * NN + j] = lo;
    }

    const int jp = j >> 1, hh = j & 1;
    g_cA[jp * 4 + 0 + hh] = -xv[0];
    g_cA[jp * 4 + 2 + hh] = -xv[1];
    g_cB[jp * 2 + hh]     = -xv[2];
}

// ---------------- Kernel A2: preassemble mma B fragments ----------------
// m16n8k16 col B frag: lane (n0=lane/4, q=lane%4) holds
//   b0={B[k0,n0],B[k0+1,n0]}, b1={B[k0+8,n0],...}, k0 = 2q (+hi/lo pair)
__global__ void __launch_bounds__(1024) bprep_kernel()
{
    const int idx = blockIdx.x * 1024 + threadIdx.x;   // KC*64*32 = 16384
    const int kc = idx >> 11, rem = idx & 2047;
    const int ks = rem >> 5, lane = rem & 31;
    const int n0 = lane >> 2, q = lane & 3;
    const unsigned int* w = reinterpret_cast<const unsigned int*>(g_wvbf);
    const int base = n0 * (NN / 2) + kc * (CJ / 2) + ks * 8 + q;
    uint4 v;
    v.x = w[base];                        // hi channel n0, k0..k0+1
    v.y = w[base + 4];                    // hi, k0+8..k0+9
    v.z = w[base + 8 * (NN / 2)];         // lo channel n0
    v.w = w[base + 8 * (NN / 2) + 4];
    g_bfrag[idx] = v;
}

__global__ void probe_kernel() {}

// ---------------- Kernel B: mask-gen + HMMA masked GEMM ----------------
// CTA = (kchunk, mtile): 128 i x 1024 j; 8 warps, warp w -> 16 i rows.
__global__ void __launch_bounds__(256) pairmma_kernel(const float* __restrict__ x)
{
    __shared__ uint4 s_bf[KSTEPS * 32];              // 32 KB B fragments
    __shared__ float4 s_cA[CJ / 2];                  //  8 KB
    __shared__ float2 s_cB[CJ / 2];                  //  4 KB
    __shared__ unsigned long long s_ci[128 * 3];     //  3 KB dup i-coords

    const int tid = threadIdx.x, wid = tid >> 5, lane = tid & 31;
    const int kc = blockIdx.x, mt = blockIdx.y;
    const int g = lane >> 2, q = lane & 3;

    {
        const uint4* gbf = g_bfrag + kc * (KSTEPS * 32);
        for (int k = tid; k < KSTEPS * 32; k += 256) s_bf[k] = gbf[k];
        const float4* ga = reinterpret_cast<const float4*>(g_cA) + kc * (CJ / 2);
        for (int k = tid; k < CJ / 2; k += 256) s_cA[k] = ga[k];
        const float2* gb = reinterpret_cast<const float2*>(g_cB) + kc * (CJ / 2);
        for (int k = tid; k < CJ / 2; k += 256) s_cB[k] = gb[k];
        if (tid < 128) {
            const int i = mt * 128 + tid;
            const float c0 = x[i * DIN + 0];
            const float c1 = x[i * DIN + 1];
            const float c2 = x[i * DIN + 2];
            unsigned long long d0, d1, d2;
            asm("mov.b64 %0, {%1, %1};" : "=l"(d0) : "f"(c0));
            asm("mov.b64 %0, {%1, %1};" : "=l"(d1) : "f"(c1));
            asm("mov.b64 %0, {%1, %1};" : "=l"(d2) : "f"(c2));
            s_ci[tid * 3 + 0] = d0;
            s_ci[tid * 3 + 1] = d1;
            s_ci[tid * 3 + 2] = d2;
        }
    }
    __syncthreads();

    // this lane's two i-rows (m16n8k16 A layout), coords duplicated in f32x2
    const int r0 = wid * 16 + g;                     // row g of warp tile
    const unsigned long long ciA0 = s_ci[r0 * 3 + 0];
    const unsigned long long ciA1 = s_ci[r0 * 3 + 1];
    const unsigned long long ciA2 = s_ci[r0 * 3 + 2];
    const unsigned long long ciB0 = s_ci[(r0 + 8) * 3 + 0];
    const unsigned long long ciB1 = s_ci[(r0 + 8) * 3 + 1];
    const unsigned long long ciB2 = s_ci[(r0 + 8) * 3 + 2];

    float d0h = 0.f, d1h = 0.f, d2h = 0.f, d3h = 0.f;   // hi channels
    float d0l = 0.f, d1l = 0.f, d2l = 0.f, d3l = 0.f;   // lo channels

    const ulonglong2* cap = reinterpret_cast<const ulonglong2*>(s_cA);
    const unsigned long long* cbp =
        reinterpret_cast<const unsigned long long*>(s_cB);

#pragma unroll 4
    for (int ks = 0; ks < KSTEPS; ks++) {
        const int p0 = ks * 8 + q;                   // j-pair (2q) of this step
        const int p1 = p0 + 4;                       // j-pair (2q+8)
        const ulonglong2 ca0 = cap[p0];              // {-x0 pair, -x1 pair}
        const unsigned long long cb0 = cbp[p0];      // {-x2 pair}
        const ulonglong2 ca1 = cap[p1];
        const unsigned long long cb1 = cbp[p1];

        unsigned int a0, a1, a2, a3;
        MASKW(a0, ciA0, ciA1, ciA2, ca0.x, ca0.y, cb0);   // rows g,   cols k0
        MASKW(a1, ciB0, ciB1, ciB2, ca0.x, ca0.y, cb0);   // rows g+8, cols k0
        MASKW(a2, ciA0, ciA1, ciA2, ca1.x, ca1.y, cb1);   // rows g,   cols k0+8
        MASKW(a3, ciB0, ciB1, ciB2, ca1.x, ca1.y, cb1);   // rows g+8, cols k0+8

        const uint4 bf = s_bf[ks * 32 + lane];
        MMA_BF16(d0h, d1h, d2h, d3h, a0, a1, a2, a3, bf.x, bf.y);
        MMA_BF16(d0l, d1l, d2l, d3l, a0, a1, a2, a3, bf.z, bf.w);
    }

    // D frag: lane holds rows {g, g+8}, channels {2q, 2q+1}; agg = hi + lo
    const int i0 = mt * 128 + r0;
    *reinterpret_cast<float2*>(&g_part[kc][i0][2 * q]) =
        make_float2(d0h + d0l, d1h + d1l);
    *reinterpret_cast<float2*>(&g_part[kc][i0 + 8][2 * q]) =
        make_float2(d2h + d2l, d3h + d3l);
}

// ---------------- Kernel C: fused chunk-reduce + final MLP ----------------
__global__ void __launch_bounds__(64) final_kernel(
    const float* __restrict__ x,
    const float* __restrict__ We, const float* __restrict__ be,
    const float* __restrict__ Wd, const float* __restrict__ bd,
    float* __restrict__ out)
{
    __shared__ float sWe[DH * 2 * DIN], sbe[DH], sWd[DIN * DH], sbd[DIN];
    const int t = threadIdx.x;
    for (int k = t; k < DH * 2 * DIN; k += 64) sWe[k] = We[k];
    if (t < DIN * DH) sWd[t] = Wd[t];
    if (t < DH) sbe[t] = be[t];
    if (t < DIN) sbd[t] = bd[t];
    __syncthreads();

    const int i = blockIdx.x * 64 + t;

    float a[8];
#pragma unroll
    for (int k = 0; k < 8; k++) a[k] = 0.0f;
#pragma unroll
    for (int c = 0; c < KC; c++) {
        const float4* p = reinterpret_cast<const float4*>(&g_part[c][i][0]);
        const float4 pa = p[0], pb = p[1];
        a[0] += pa.x; a[1] += pa.y; a[2] += pa.z; a[3] += pa.w;
        a[4] += pb.x; a[5] += pb.y; a[6] += pb.z; a[7] += pb.w;
    }
    // subtract self contribution (self-pair always passes d=0 <= cutoff)
    const float4 wa = g_wv[2 * i], wb = g_wv[2 * i + 1];
    a[0] -= wa.x; a[1] -= wa.y; a[2] -= wa.z; a[3] -= wa.w;
    a[4] -= wb.x; a[5] -= wb.y; a[6] -= wb.z;
    const float denom = a[7] - wb.w;
    const float inv = 1.0f / fmaxf(denom, 1e-30f);

    float agg[DIN];
#pragma unroll
    for (int k = 0; k < DIN; k++) agg[k] = a[k] * inv;

    float xv[DIN];
#pragma unroll
    for (int k = 0; k < DIN; k++) xv[k] = x[i * DIN + k];

    float codes[DH];
#pragma unroll
    for (int c = 0; c < DH; c++) {
        float z = sbe[c];
#pragma unroll
        for (int k = 0; k < DIN; k++) z += sWe[c * (2 * DIN) + k] * xv[k];
#pragma unroll
        for (int k = 0; k < DIN; k++) z += sWe[c * (2 * DIN) + DIN + k] * agg[k];
        codes[c] = leaky(z);
    }
#pragma unroll
    for (int d = 0; d < DIN; d++) {
        float z = sbd[d];
#pragma unroll
        for (int c = 0; c < DH; c++) z += sWd[d * DH + c] * codes[c];
        out[i * DIN + d] = z;
    }
}

// ---------------- launch ----------------
extern "C" void kernel_launch(void* const* d_in, const int* in_sizes, int n_in,
                              void* d_out, int out_size)
{
    const float* x  = (const float*)d_in[0];
    const float* W1 = (const float*)d_in[1];
    const float* b1 = (const float*)d_in[2];
    const float* W2 = (const float*)d_in[3];
    const float* b2 = (const float*)d_in[4];
    const float* W3 = (const float*)d_in[5];
    const float* b3 = (const float*)d_in[6];
    const float* We = (const float*)d_in[7];
    const float* be = (const float*)d_in[8];
    const float* Wd = (const float*)d_in[9];
    const float* bd = (const float*)d_in[10];
    float* out = (float*)d_out;

    prep_kernel<<<NN / 32, 32>>>(x, W1, b1, W2, b2, W3, b3);   // launch 1
    bprep_kernel<<<KC * KSTEPS * 32 / 1024, 1024>>>();          // launch 2
    probe_kernel<<<1, 32>>>();                                  // launch 3
    probe_kernel<<<1, 32>>>();                                  // launch 4
    probe_kernel<<<1, 32>>>();                                  // launch 5
    dim3 grid(KC, MT);
    pairmma_kernel<<<grid, 256>>>(x);                           // launch 6 (ncu -s 5)
    final_kernel<<<NN / 64, 64>>>(x, We, be, Wd, bd, out);      // launch 7
}

// round 11
// speedup vs baseline: 1.5602x; 1.5602x over previous
#include <cuda_runtime.h>
#include <cuda_bf16.h>

#define NN 8192
#define DIN 7
#define DH 8
#define DOUTK 23
#define KC 8                  /* K-chunks (grid.x), 1024 j each */
#define MT 64                 /* M-tiles of 128 i  (grid.y)     */
#define CJ 1024               /* j per chunk                    */
#define KSTEPS (CJ / 16)      /* 64 mma K-steps per chunk       */

// -------- device scratch (no allocations allowed) --------
__device__ float g_cA[(NN / 2) * 4];         // per j-pair: {-x0a,-x0b,-x1a,-x1b}
__device__ float g_cB[(NN / 2) * 2];         // per j-pair: {-x2a,-x2b}
__device__ __nv_bfloat16 g_wvbf[8 * NN];     // rows 0-6 = w*vals, row 7 = w
__device__ uint2 g_bfrag[KC * KSTEPS * 32];  // preassembled B fragments
__device__ float g_part[KC][NN][8];          // K-chunk partial accumulators

__device__ __forceinline__ float leaky(float v) {
    return v >= 0.0f ? v : 0.01f * v;
}

// one bf16x2 mask word: lanes of f32x2 = (j even, j odd)
// d = (|ci0-cj0| + |ci1-cj1|) + |ci2-cj2|  -- reference fp32 order, j pre-negated
#define MASKW(out, ci0, ci1, ci2, cj0, cj1, cj2)                          \
    asm("{\n\t"                                                           \
        ".reg .b64 u0,u1,u2,dd;\n\t"                                      \
        ".reg .b32 ea,eb,m0,m1;\n\t"                                      \
        ".reg .pred pa,pb;\n\t"                                           \
        "add.rn.f32x2 u0, %1, %4;\n\t"                                    \
        "add.rn.f32x2 u1, %2, %5;\n\t"                                    \
        "add.rn.f32x2 u2, %3, %6;\n\t"                                    \
        "and.b64 u0, u0, 0x7FFFFFFF7FFFFFFF;\n\t"                         \
        "and.b64 u1, u1, 0x7FFFFFFF7FFFFFFF;\n\t"                         \
        "and.b64 u2, u2, 0x7FFFFFFF7FFFFFFF;\n\t"                         \
        "add.rn.f32x2 dd, u0, u1;\n\t"                                    \
        "add.rn.f32x2 dd, dd, u2;\n\t"                                    \
        "mov.b64 {ea,eb}, dd;\n\t"                                        \
        "setp.le.u32 pa, ea, 0x40666666;\n\t"                             \
        "setp.le.u32 pb, eb, 0x40666666;\n\t"                             \
        "selp.b32 m0, 0x00003F80, 0, pa;\n\t"                             \
        "selp.b32 m1, 0x3F800000, 0, pb;\n\t"                             \
        "or.b32 %0, m0, m1;\n\t"                                          \
        "}"                                                               \
        : "=r"(out)                                                       \
        : "l"(ci0), "l"(ci1), "l"(ci2), "l"(cj0), "l"(cj1), "l"(cj2))

#define MMA_BF16(d0, d1, d2, d3, a0, a1, a2, a3, b0, b1)                  \
    asm("mma.sync.aligned.m16n8k16.row.col.f32.bf16.bf16.f32 "            \
        "{%0,%1,%2,%3}, {%4,%5,%6,%7}, {%8,%9}, {%0,%1,%2,%3};"           \
        : "+f"(d0), "+f"(d1), "+f"(d2), "+f"(d3)                          \
        : "r"(a0), "r"(a1), "r"(a2), "r"(a3), "r"(b0), "r"(b1))

// ---------------- Kernel A: per-node MLP + exp weights ----------------
__global__ void __launch_bounds__(32) prep_kernel(
    const float* __restrict__ x,
    const float* __restrict__ W1, const float* __restrict__ b1,
    const float* __restrict__ W2, const float* __restrict__ b2,
    const float* __restrict__ W3, const float* __restrict__ b3)
{
    __shared__ float sW1[DH * DIN], sb1[DH], sW2[DH * DH], sb2[DH],
                     sW3[DOUTK * DH], sb3[DOUTK];
    __shared__ float sx[32 * DIN];
    const int t = threadIdx.x;
    {
        const float* xb = x + blockIdx.x * 32 * DIN;
        for (int k = t; k < 32 * DIN; k += 32) sx[k] = xb[k];
        for (int k = t; k < DH * DIN; k += 32) sW1[k] = W1[k];
        for (int k = t; k < DH * DH; k += 32) sW2[k] = W2[k];
        for (int k = t; k < DOUTK * DH; k += 32) sW3[k] = W3[k];
        if (t < DH) { sb1[t] = b1[t]; sb2[t] = b2[t]; }
        if (t < DOUTK) sb3[t] = b3[t];
    }
    __syncthreads();

    const int j = blockIdx.x * 32 + t;

    float xv[DIN];
#pragma unroll
    for (int k = 0; k < DIN; k++) xv[k] = sx[t * DIN + k];

    float h1[DH];
#pragma unroll
    for (int c = 0; c < DH; c++) {
        float z = sb1[c];
#pragma unroll
        for (int k = 0; k < DIN; k++) z += sW1[c * DIN + k] * xv[k];
        h1[c] = leaky(z);
    }
    float h2[DH];
#pragma unroll
    for (int c = 0; c < DH; c++) {
        float z = sb2[c];
#pragma unroll
        for (int k = 0; k < DH; k++) z += sW2[c * DH + k] * h1[k];
        h2[c] = leaky(z);
    }
    float h3[DOUTK];
#pragma unroll
    for (int c = 0; c < DOUTK; c++) {
        float z = sb3[c];
#pragma unroll
        for (int k = 0; k < DH; k++) z += sW3[c * DH + k] * h2[k];
        h3[c] = z;   // layer 3 is linear
    }

    float s = 0.0f;
#pragma unroll
    for (int k = 0; k < 8; k++) s += h3[DIN + k] * h3[DIN + 8 + k];
    const float w = expf(s);

    // bf16 aggregation channels (w*vals0..6, w)
#pragma unroll
    for (int c = 0; c < 8; c++) {
        const float v = (c < 7) ? w * h3[c] : w;
        g_wvbf[c * NN + j] = __float2bfloat16(v);
    }

    const int jp = j >> 1, hh = j & 1;
    g_cA[jp * 4 + 0 + hh] = -xv[0];
    g_cA[jp * 4 + 2 + hh] = -xv[1];
    g_cB[jp * 2 + hh]     = -xv[2];
}

// ---------------- Kernel A2: preassemble mma B fragments ----------------
// m16n8k16 col B frag: lane (n0=lane/4, q=lane%4) holds
//   b0={B[k0,n0],B[k0+1,n0]}, b1={B[k0+8,n0],B[k0+9,n0]}, k0 = 2q
__global__ void __launch_bounds__(1024) bprep_kernel()
{
    const int idx = blockIdx.x * 1024 + threadIdx.x;   // KC*64*32 = 16384
    const int kc = idx >> 11, rem = idx & 2047;
    const int ks = rem >> 5, lane = rem & 31;
    const int n0 = lane >> 2, q = lane & 3;
    const unsigned int* w = reinterpret_cast<const unsigned int*>(g_wvbf);
    const int base = n0 * (NN / 2) + kc * (CJ / 2) + ks * 8 + q;
    uint2 v;
    v.x = w[base];                        // channel n0, k0..k0+1
    v.y = w[base + 4];                    // channel n0, k0+8..k0+9
    g_bfrag[idx] = v;
}

// ---------------- Kernel B: mask-gen + HMMA masked GEMM ----------------
// CTA = (kchunk, mtile): 128 i x 1024 j; 8 warps, warp w -> 16 i rows.
__global__ void __launch_bounds__(256) pairmma_kernel(const float* __restrict__ x)
{
    __shared__ uint2 s_bf[KSTEPS * 32];              // 16 KB B fragments
    __shared__ float4 s_cA[CJ / 2];                  //  8 KB
    __shared__ float2 s_cB[CJ / 2];                  //  4 KB
    __shared__ unsigned long long s_ci[128 * 3];     //  3 KB dup i-coords

    const int tid = threadIdx.x, wid = tid >> 5, lane = tid & 31;
    const int kc = blockIdx.x, mt = blockIdx.y;
    const int g = lane >> 2, q = lane & 3;

    {
        const uint2* gbf = g_bfrag + kc * (KSTEPS * 32);
        for (int k = tid; k < KSTEPS * 32; k += 256) s_bf[k] = gbf[k];
        const float4* ga = reinterpret_cast<const float4*>(g_cA) + kc * (CJ / 2);
        for (int k = tid; k < CJ / 2; k += 256) s_cA[k] = ga[k];
        const float2* gb = reinterpret_cast<const float2*>(g_cB) + kc * (CJ / 2);
        for (int k = tid; k < CJ / 2; k += 256) s_cB[k] = gb[k];
        if (tid < 128) {
            const int i = mt * 128 + tid;
            const float c0 = x[i * DIN + 0];
            const float c1 = x[i * DIN + 1];
            const float c2 = x[i * DIN + 2];
            unsigned long long d0, d1, d2;
            asm("mov.b64 %0, {%1, %1};" : "=l"(d0) : "f"(c0));
            asm("mov.b64 %0, {%1, %1};" : "=l"(d1) : "f"(c1));
            asm("mov.b64 %0, {%1, %1};" : "=l"(d2) : "f"(c2));
            s_ci[tid * 3 + 0] = d0;
            s_ci[tid * 3 + 1] = d1;
            s_ci[tid * 3 + 2] = d2;
        }
    }
    __syncthreads();

    // this lane's two i-rows (m16n8k16 A layout), coords duplicated in f32x2
    const int r0 = wid * 16 + g;                     // row g of warp tile
    const unsigned long long ciA0 = s_ci[r0 * 3 + 0];
    const unsigned long long ciA1 = s_ci[r0 * 3 + 1];
    const unsigned long long ciA2 = s_ci[r0 * 3 + 2];
    const unsigned long long ciB0 = s_ci[(r0 + 8) * 3 + 0];
    const unsigned long long ciB1 = s_ci[(r0 + 8) * 3 + 1];
    const unsigned long long ciB2 = s_ci[(r0 + 8) * 3 + 2];

    // two accumulator groups (even/odd K-steps) break the HMMA dep chain
    float e0 = 0.f, e1 = 0.f, e2 = 0.f, e3 = 0.f;
    float o0 = 0.f, o1 = 0.f, o2 = 0.f, o3 = 0.f;

    const ulonglong2* cap = reinterpret_cast<const ulonglong2*>(s_cA);
    const unsigned long long* cbp =
        reinterpret_cast<const unsigned long long*>(s_cB);

#pragma unroll 8
    for (int ks = 0; ks < KSTEPS; ks++) {
        const int p0 = ks * 8 + q;                   // j-pair (2q) of this step
        const int p1 = p0 + 4;                       // j-pair (2q+8)
        const ulonglong2 ca0 = cap[p0];              // {-x0 pair, -x1 pair}
        const unsigned long long cb0 = cbp[p0];      // {-x2 pair}
        const ulonglong2 ca1 = cap[p1];
        const unsigned long long cb1 = cbp[p1];

        unsigned int a0, a1, a2, a3;
        MASKW(a0, ciA0, ciA1, ciA2, ca0.x, ca0.y, cb0);   // rows g,   cols k0
        MASKW(a1, ciB0, ciB1, ciB2, ca0.x, ca0.y, cb0);   // rows g+8, cols k0
        MASKW(a2, ciA0, ciA1, ciA2, ca1.x, ca1.y, cb1);   // rows g,   cols k0+8
        MASKW(a3, ciB0, ciB1, ciB2, ca1.x, ca1.y, cb1);   // rows g+8, cols k0+8

        const uint2 bf = s_bf[ks * 32 + lane];
        if (ks & 1) {
            MMA_BF16(o0, o1, o2, o3, a0, a1, a2, a3, bf.x, bf.y);
        } else {
            MMA_BF16(e0, e1, e2, e3, a0, a1, a2, a3, bf.x, bf.y);
        }
    }

    // D frag: lane holds rows {g, g+8}, channels {2q, 2q+1}
    const int i0 = mt * 128 + r0;
    *reinterpret_cast<float2*>(&g_part[kc][i0][2 * q]) =
        make_float2(e0 + o0, e1 + o1);
    *reinterpret_cast<float2*>(&g_part[kc][i0 + 8][2 * q]) =
        make_float2(e2 + o2, e3 + o3);
}

// ---------------- Kernel C: fused chunk-reduce + final MLP ----------------
__global__ void __launch_bounds__(64) final_kernel(
    const float* __restrict__ x,
    const float* __restrict__ We, const float* __restrict__ be,
    const float* __restrict__ Wd, const float* __restrict__ bd,
    float* __restrict__ out)
{
    __shared__ float sWe[DH * 2 * DIN], sbe[DH], sWd[DIN * DH], sbd[DIN];
    const int t = threadIdx.x;
    for (int k = t; k < DH * 2 * DIN; k += 64) sWe[k] = We[k];
    if (t < DIN * DH) sWd[t] = Wd[t];
    if (t < DH) sbe[t] = be[t];
    if (t < DIN) sbd[t] = bd[t];
    __syncthreads();

    const int i = blockIdx.x * 64 + t;

    float a[8];
#pragma unroll
    for (int k = 0; k < 8; k++) a[k] = 0.0f;
#pragma unroll
    for (int c = 0; c < KC; c++) {
        const float4* p = reinterpret_cast<const float4*>(&g_part[c][i][0]);
        const float4 pa = p[0], pb = p[1];
        a[0] += pa.x; a[1] += pa.y; a[2] += pa.z; a[3] += pa.w;
        a[4] += pb.x; a[5] += pb.y; a[6] += pb.z; a[7] += pb.w;
    }
    // subtract self contribution exactly as the MMA added it (bf16-rounded);
    // self-pair always passes (d=0 <= cutoff)
#pragma unroll
    for (int c = 0; c < 8; c++)
        a[c] -= __bfloat162float(g_wvbf[c * NN + i]);
    const float denom = a[7];
    const float inv = 1.0f / fmaxf(denom, 1e-30f);

    float agg[DIN];
#pragma unroll
    for (int k = 0; k < DIN; k++) agg[k] = a[k] * inv;

    float xv[DIN];
#pragma unroll
    for (int k = 0; k < DIN; k++) xv[k] = x[i * DIN + k];

    float codes[DH];
#pragma unroll
    for (int c = 0; c < DH; c++) {
        float z = sbe[c];
#pragma unroll
        for (int k = 0; k < DIN; k++) z += sWe[c * (2 * DIN) + k] * xv[k];
#pragma unroll
        for (int k = 0; k < DIN; k++) z += sWe[c * (2 * DIN) + DIN + k] * agg[k];
        codes[c] = leaky(z);
    }
#pragma unroll
    for (int d = 0; d < DIN; d++) {
        float z = sbd[d];
#pragma unroll
        for (int c = 0; c < DH; c++) z += sWd[d * DH + c] * codes[c];
        out[i * DIN + d] = z;
    }
}

// ---------------- launch ----------------
extern "C" void kernel_launch(void* const* d_in, const int* in_sizes, int n_in,
                              void* d_out, int out_size)
{
    const float* x  = (const float*)d_in[0];
    const float* W1 = (const float*)d_in[1];
    const float* b1 = (const float*)d_in[2];
    const float* W2 = (const float*)d_in[3];
    const float* b2 = (const float*)d_in[4];
    const float* W3 = (const float*)d_in[5];
    const float* b3 = (const float*)d_in[6];
    const float* We = (const float*)d_in[7];
    const float* be = (const float*)d_in[8];
    const float* Wd = (const float*)d_in[9];
    const float* bd = (const float*)d_in[10];
    float* out = (float*)d_out;

    prep_kernel<<<NN / 32, 32>>>(x, W1, b1, W2, b2, W3, b3);
    bprep_kernel<<<KC * KSTEPS * 32 / 1024, 1024>>>();
    dim3 grid(KC, MT);
    pairmma_kernel<<<grid, 256>>>(x);
    final_kernel<<<NN / 64, 64>>>(x, We, be, Wd, bd, out);
}

// round 12
// speedup vs baseline: 1.6304x; 1.0450x over previous
#include <cuda_runtime.h>
#include <cuda_bf16.h>

#define NN 8192
#define DIN 7
#define DH 8
#define DOUTK 23
#define KC 8                  /* K-chunks (grid.x), 1024 j each */
#define MT 64                 /* M-tiles of 128 i  (grid.y)     */
#define CJ 1024               /* j per chunk                    */
#define KSTEPS (CJ / 16)      /* 64 mma K-steps per chunk       */

// -------- device scratch (no allocations allowed) --------
__device__ float g_cA[(NN / 2) * 4];         // per j-pair: {-x0a,-x0b,-x1a,-x1b}
__device__ float g_cB[(NN / 2) * 2];         // per j-pair: {-x2a,-x2b}
__device__ __nv_bfloat16 g_wvbf[8 * NN];     // rows 0-6 = w*vals, row 7 = w
__device__ uint2 g_bfrag[KC * KSTEPS * 32];  // preassembled B fragments
__device__ float g_part[KC][NN][8];          // K-chunk partial accumulators
__device__ int g_cnt[MT];                    // per-mtile completion counters (0-init, self-reset)

__device__ __forceinline__ float leaky(float v) {
    return v >= 0.0f ? v : 0.01f * v;
}

// one bf16x2 mask word: lanes of f32x2 = (j even, j odd)
// d = (|ci0-cj0| + |ci1-cj1|) + |ci2-cj2|  -- reference fp32 order, j pre-negated
#define MASKW(out, ci0, ci1, ci2, cj0, cj1, cj2)                          \
    asm("{\n\t"                                                           \
        ".reg .b64 u0,u1,u2,dd;\n\t"                                      \
        ".reg .b32 ea,eb,m0,m1;\n\t"                                      \
        ".reg .pred pa,pb;\n\t"                                           \
        "add.rn.f32x2 u0, %1, %4;\n\t"                                    \
        "add.rn.f32x2 u1, %2, %5;\n\t"                                    \
        "add.rn.f32x2 u2, %3, %6;\n\t"                                    \
        "and.b64 u0, u0, 0x7FFFFFFF7FFFFFFF;\n\t"                         \
        "and.b64 u1, u1, 0x7FFFFFFF7FFFFFFF;\n\t"                         \
        "and.b64 u2, u2, 0x7FFFFFFF7FFFFFFF;\n\t"                         \
        "add.rn.f32x2 dd, u0, u1;\n\t"                                    \
        "add.rn.f32x2 dd, dd, u2;\n\t"                                    \
        "mov.b64 {ea,eb}, dd;\n\t"                                        \
        "setp.le.u32 pa, ea, 0x40666666;\n\t"                             \
        "setp.le.u32 pb, eb, 0x40666666;\n\t"                             \
        "selp.b32 m0, 0x00003F80, 0, pa;\n\t"                             \
        "selp.b32 m1, 0x3F800000, 0, pb;\n\t"                             \
        "or.b32 %0, m0, m1;\n\t"                                          \
        "}"                                                               \
        : "=r"(out)                                                       \
        : "l"(ci0), "l"(ci1), "l"(ci2), "l"(cj0), "l"(cj1), "l"(cj2))

#define MMA_BF16(d0, d1, d2, d3, a0, a1, a2, a3, b0, b1)                  \
    asm("mma.sync.aligned.m16n8k16.row.col.f32.bf16.bf16.f32 "            \
        "{%0,%1,%2,%3}, {%4,%5,%6,%7}, {%8,%9}, {%0,%1,%2,%3};"           \
        : "+f"(d0), "+f"(d1), "+f"(d2), "+f"(d3)                          \
        : "r"(a0), "r"(a1), "r"(a2), "r"(a3), "r"(b0), "r"(b1))

// ------- Kernel A: per-node MLP + exp weights + fused B-fragment build -------
__global__ void __launch_bounds__(32) prep_kernel(
    const float* __restrict__ x,
    const float* __restrict__ W1, const float* __restrict__ b1,
    const float* __restrict__ W2, const float* __restrict__ b2,
    const float* __restrict__ W3, const float* __restrict__ b3)
{
    __shared__ float sW1[DH * DIN], sb1[DH], sW2[DH * DH], sb2[DH],
                     sW3[DOUTK * DH], sb3[DOUTK];
    __shared__ float sx[32 * DIN];
    __shared__ unsigned short s_wvh[8][32];   // bf16 bits, [channel][j-local]
    const int t = threadIdx.x;
    {
        const float* xb = x + blockIdx.x * 32 * DIN;
        for (int k = t; k < 32 * DIN; k += 32) sx[k] = xb[k];
        for (int k = t; k < DH * DIN; k += 32) sW1[k] = W1[k];
        for (int k = t; k < DH * DH; k += 32) sW2[k] = W2[k];
        for (int k = t; k < DOUTK * DH; k += 32) sW3[k] = W3[k];
        if (t < DH) { sb1[t] = b1[t]; sb2[t] = b2[t]; }
        if (t < DOUTK) sb3[t] = b3[t];
    }
    __syncthreads();

    const int j = blockIdx.x * 32 + t;

    float xv[DIN];
#pragma unroll
    for (int k = 0; k < DIN; k++) xv[k] = sx[t * DIN + k];

    float h1[DH];
#pragma unroll
    for (int c = 0; c < DH; c++) {
        float z = sb1[c];
#pragma unroll
        for (int k = 0; k < DIN; k++) z += sW1[c * DIN + k] * xv[k];
        h1[c] = leaky(z);
    }
    float h2[DH];
#pragma unroll
    for (int c = 0; c < DH; c++) {
        float z = sb2[c];
#pragma unroll
        for (int k = 0; k < DH; k++) z += sW2[c * DH + k] * h1[k];
        h2[c] = leaky(z);
    }
    float h3[DOUTK];
#pragma unroll
    for (int c = 0; c < DOUTK; c++) {
        float z = sb3[c];
#pragma unroll
        for (int k = 0; k < DH; k++) z += sW3[c * DH + k] * h2[k];
        h3[c] = z;   // layer 3 is linear
    }

    float s = 0.0f;
#pragma unroll
    for (int k = 0; k < 8; k++) s += h3[DIN + k] * h3[DIN + 8 + k];
    const float w = expf(s);

    // bf16 aggregation channels (w*vals0..6, w)
#pragma unroll
    for (int c = 0; c < 8; c++) {
        const float v = (c < 7) ? w * h3[c] : w;
        const __nv_bfloat16 bf = __float2bfloat16(v);
        g_wvbf[c * NN + j] = bf;                       // for self-subtraction
        s_wvh[c][t] = __bfloat16_as_ushort(bf);
    }

    const int jp = j >> 1, hh = j & 1;
    g_cA[jp * 4 + 0 + hh] = -xv[0];
    g_cA[jp * 4 + 2 + hh] = -xv[1];
    g_cB[jp * 2 + hh]     = -xv[2];

    __syncthreads();

    // ---- fused B-fragment assembly: this CTA covers 2 K-steps of 16 j ----
    // m16n8k16 col B frag, lane (n0=lane/4, q=lane%4):
    //   v.x = {B[k0,n0],B[k0+1,n0]}, v.y = {B[k0+8,n0],B[k0+9,n0]}, k0=2q
    const int j0 = blockIdx.x * 32;
    const int kc = j0 >> 10;
    const int ks0 = (j0 & 1023) >> 4;
#pragma unroll
    for (int e = t; e < 64; e += 32) {
        const int lks = e >> 5, lane = e & 31;
        const int n0 = lane >> 2, q = lane & 3;
        const int bj = lks * 16 + 2 * q;
        uint2 v;
        v.x = (unsigned int)s_wvh[n0][bj] |
              ((unsigned int)s_wvh[n0][bj + 1] << 16);
        v.y = (unsigned int)s_wvh[n0][bj + 8] |
              ((unsigned int)s_wvh[n0][bj + 9] << 16);
        g_bfrag[kc * (KSTEPS * 32) + (ks0 + lks) * 32 + lane] = v;
    }
}

// ------- Kernel B: mask-gen + HMMA GEMM + last-CTA fused reduce/final -------
// CTA = (kchunk, mtile): 128 i x 1024 j; 8 warps, warp w -> 16 i rows.
__global__ void __launch_bounds__(256) pairmma_kernel(
    const float* __restrict__ x,
    const float* __restrict__ We, const float* __restrict__ be,
    const float* __restrict__ Wd, const float* __restrict__ bd,
    float* __restrict__ out)
{
    __shared__ uint2 s_bf[KSTEPS * 32];              // 16 KB B fragments
    __shared__ float4 s_cA[CJ / 2];                  //  8 KB
    __shared__ float2 s_cB[CJ / 2];                  //  4 KB
    __shared__ unsigned long long s_ci[128 * 3];     //  3 KB dup i-coords
    __shared__ float sWe[DH * 2 * DIN], sbe[DH], sWd[DIN * DH], sbd[DIN];
    __shared__ int s_last;

    const int tid = threadIdx.x, wid = tid >> 5, lane = tid & 31;
    const int kc = blockIdx.x, mt = blockIdx.y;
    const int g = lane >> 2, q = lane & 3;

    {
        const uint2* gbf = g_bfrag + kc * (KSTEPS * 32);
        for (int k = tid; k < KSTEPS * 32; k += 256) s_bf[k] = gbf[k];
        const float4* ga = reinterpret_cast<const float4*>(g_cA) + kc * (CJ / 2);
        for (int k = tid; k < CJ / 2; k += 256) s_cA[k] = ga[k];
        const float2* gb = reinterpret_cast<const float2*>(g_cB) + kc * (CJ / 2);
        for (int k = tid; k < CJ / 2; k += 256) s_cB[k] = gb[k];
        if (tid < 128) {
            const int i = mt * 128 + tid;
            const float c0 = x[i * DIN + 0];
            const float c1 = x[i * DIN + 1];
            const float c2 = x[i * DIN + 2];
            unsigned long long d0, d1, d2;
            asm("mov.b64 %0, {%1, %1};" : "=l"(d0) : "f"(c0));
            asm("mov.b64 %0, {%1, %1};" : "=l"(d1) : "f"(c1));
            asm("mov.b64 %0, {%1, %1};" : "=l"(d2) : "f"(c2));
            s_ci[tid * 3 + 0] = d0;
            s_ci[tid * 3 + 1] = d1;
            s_ci[tid * 3 + 2] = d2;
        }
    }
    __syncthreads();

    // this lane's two i-rows (m16n8k16 A layout), coords duplicated in f32x2
    const int r0 = wid * 16 + g;                     // row g of warp tile
    const unsigned long long ciA0 = s_ci[r0 * 3 + 0];
    const unsigned long long ciA1 = s_ci[r0 * 3 + 1];
    const unsigned long long ciA2 = s_ci[r0 * 3 + 2];
    const unsigned long long ciB0 = s_ci[(r0 + 8) * 3 + 0];
    const unsigned long long ciB1 = s_ci[(r0 + 8) * 3 + 1];
    const unsigned long long ciB2 = s_ci[(r0 + 8) * 3 + 2];

    // two accumulator groups (even/odd K-steps) break the HMMA dep chain
    float e0 = 0.f, e1 = 0.f, e2 = 0.f, e3 = 0.f;
    float o0 = 0.f, o1 = 0.f, o2 = 0.f, o3 = 0.f;

    const ulonglong2* cap = reinterpret_cast<const ulonglong2*>(s_cA);
    const unsigned long long* cbp =
        reinterpret_cast<const unsigned long long*>(s_cB);

#pragma unroll 8
    for (int ks = 0; ks < KSTEPS; ks++) {
        const int p0 = ks * 8 + q;                   // j-pair (2q) of this step
        const int p1 = p0 + 4;                       // j-pair (2q+8)
        const ulonglong2 ca0 = cap[p0];              // {-x0 pair, -x1 pair}
        const unsigned long long cb0 = cbp[p0];      // {-x2 pair}
        const ulonglong2 ca1 = cap[p1];
        const unsigned long long cb1 = cbp[p1];

        unsigned int a0, a1, a2, a3;
        MASKW(a0, ciA0, ciA1, ciA2, ca0.x, ca0.y, cb0);   // rows g,   cols k0
        MASKW(a1, ciB0, ciB1, ciB2, ca0.x, ca0.y, cb0);   // rows g+8, cols k0
        MASKW(a2, ciA0, ciA1, ciA2, ca1.x, ca1.y, cb1);   // rows g,   cols k0+8
        MASKW(a3, ciB0, ciB1, ciB2, ca1.x, ca1.y, cb1);   // rows g+8, cols k0+8

        const uint2 bf = s_bf[ks * 32 + lane];
        if (ks & 1) {
            MMA_BF16(o0, o1, o2, o3, a0, a1, a2, a3, bf.x, bf.y);
        } else {
            MMA_BF16(e0, e1, e2, e3, a0, a1, a2, a3, bf.x, bf.y);
        }
    }

    // D frag: lane holds rows {g, g+8}, channels {2q, 2q+1}
    const int i0 = mt * 128 + r0;
    *reinterpret_cast<float2*>(&g_part[kc][i0][2 * q]) =
        make_float2(e0 + o0, e1 + o1);
    *reinterpret_cast<float2*>(&g_part[kc][i0 + 8][2 * q]) =
        make_float2(e2 + o2, e3 + o3);

    // ---- last-CTA-per-mtile: fused chunk-reduce + final MLP ----
    __threadfence();
    __syncthreads();
    if (tid == 0) {
        const int old = atomicAdd(&g_cnt[mt], 1);
        s_last = (old == KC - 1) ? 1 : 0;
    }
    __syncthreads();
    if (!s_last) return;

    // stage tiny weights
    for (int k = tid; k < DH * 2 * DIN; k += 256) sWe[k] = We[k];
    if (tid < DIN * DH) sWd[tid] = Wd[tid];
    if (tid < DH) sbe[tid] = be[tid];
    if (tid < DIN) sbd[tid] = bd[tid];
    __syncthreads();

    if (tid < 128) {
        const int i = mt * 128 + tid;

        float a[8];
#pragma unroll
        for (int k = 0; k < 8; k++) a[k] = 0.0f;
#pragma unroll
        for (int c = 0; c < KC; c++) {
            const float4* p = reinterpret_cast<const float4*>(&g_part[c][i][0]);
            const float4 pa = p[0], pb = p[1];
            a[0] += pa.x; a[1] += pa.y; a[2] += pa.z; a[3] += pa.w;
            a[4] += pb.x; a[5] += pb.y; a[6] += pb.z; a[7] += pb.w;
        }
        // subtract self contribution exactly as the MMA added it (bf16-rounded)
#pragma unroll
        for (int c = 0; c < 8; c++)
            a[c] -= __bfloat162float(g_wvbf[c * NN + i]);
        const float inv = 1.0f / fmaxf(a[7], 1e-30f);

        float agg[DIN];
#pragma unroll
        for (int k = 0; k < DIN; k++) agg[k] = a[k] * inv;

        float xv[DIN];
#pragma unroll
        for (int k = 0; k < DIN; k++) xv[k] = x[i * DIN + k];

        float codes[DH];
#pragma unroll
        for (int c = 0; c < DH; c++) {
            float z = sbe[c];
#pragma unroll
            for (int k = 0; k < DIN; k++) z += sWe[c * (2 * DIN) + k] * xv[k];
#pragma unroll
            for (int k = 0; k < DIN; k++)
                z += sWe[c * (2 * DIN) + DIN + k] * agg[k];
            codes[c] = leaky(z);
        }
#pragma unroll
        for (int d = 0; d < DIN; d++) {
            float z = sbd[d];
#pragma unroll
            for (int c = 0; c < DH; c++) z += sWd[d * DH + c] * codes[c];
            out[i * DIN + d] = z;
        }
    }
    if (tid == 0) g_cnt[mt] = 0;   // self-reset for next graph replay
}

// ---------------- launch ----------------
extern "C" void kernel_launch(void* const* d_in, const int* in_sizes, int n_in,
                              void* d_out, int out_size)
{
    const float* x  = (const float*)d_in[0];
    const float* W1 = (const float*)d_in[1];
    const float* b1 = (const float*)d_in[2];
    const float* W2 = (const float*)d_in[3];
    const float* b2 = (const float*)d_in[4];
    const float* W3 = (const float*)d_in[5];
    const float* b3 = (const float*)d_in[6];
    const float* We = (const float*)d_in[7];
    const float* be = (const float*)d_in[8];
    const float* Wd = (const float*)d_in[9];
    const float* bd = (const float*)d_in[10];
    float* out = (float*)d_out;

    prep_kernel<<<NN / 32, 32>>>(x, W1, b1, W2, b2, W3, b3);
    dim3 grid(KC, MT);
    pairmma_kernel<<<grid, 256>>>(x, We, be, Wd, bd, out);
}

// round 13
// speedup vs baseline: 2.0477x; 1.2560x over previous
#include <cuda_runtime.h>
#include <cuda_bf16.h>

#define NN 8192
#define DIN 7
#define DH 8
#define DOUTK 23
#define KC 8                  /* K-chunks (grid.x), 1024 j each */
#define MT 64                 /* M-tiles of 128 i  (grid.y)     */
#define CJ 1024               /* j per chunk                    */
#define KSTEPS (CJ / 16)      /* 64 mma K-steps per chunk       */

// -------- device scratch (no allocations allowed) --------
__device__ float g_cA[(NN / 2) * 4];         // per j-pair: {-x0a,-x0b,-x1a,-x1b}
__device__ float g_cB[(NN / 2) * 2];         // per j-pair: {-x2a,-x2b}
__device__ __nv_bfloat16 g_wvbf[8 * NN];     // rows 0-6 = w*vals, row 7 = w
__device__ uint2 g_bfrag[KC * KSTEPS * 32];  // preassembled B fragments
__device__ float g_part[KC][NN][8];          // K-chunk partial accumulators
__device__ int g_cnt[MT];                    // per-mtile counters (0-init, self-reset)

__device__ __forceinline__ float leaky(float v) {
    return v >= 0.0f ? v : 0.01f * v;
}

// one bf16x2 mask word: lanes of f32x2 = (j even, j odd)
// d = (|ci0-cj0| + |ci1-cj1|) + |ci2-cj2|  -- reference fp32 order, j pre-negated.
// Threshold via FFMA.SAT: m = sat(d*(-2^100) + C'*2^100), C' = nextafter(3.6f).
// Product is exact (pow2 scale) => m>0 <=> d < C' <=> d <= 3.6f bit-exactly;
// smallest positive value 2^100*ulp(3.6) ~ 3e23 saturates to 1.0.
//   -2^100   = 0fF1800000
//   C'*2^100 = 0f72666667   (0x40666667 scaled by 2^100, exact)
#define MASKW(out, ci0, ci1, ci2, cj0, cj1, cj2)                          \
    asm("{\n\t"                                                           \
        ".reg .b64 u0,u1,u2;\n\t"                                         \
        ".reg .f32 x0,x1,x2,y0,y1,y2,de,dq,me,mq;\n\t"                    \
        "add.rn.f32x2 u0, %1, %4;\n\t"                                    \
        "add.rn.f32x2 u1, %2, %5;\n\t"                                    \
        "add.rn.f32x2 u2, %3, %6;\n\t"                                    \
        "mov.b64 {x0,y0}, u0;\n\t"                                        \
        "mov.b64 {x1,y1}, u1;\n\t"                                        \
        "mov.b64 {x2,y2}, u2;\n\t"                                        \
        "abs.f32 x0, x0;\n\t"                                             \
        "abs.f32 x1, x1;\n\t"                                             \
        "abs.f32 x2, x2;\n\t"                                             \
        "abs.f32 y0, y0;\n\t"                                             \
        "abs.f32 y1, y1;\n\t"                                             \
        "abs.f32 y2, y2;\n\t"                                             \
        "add.rn.f32 de, x0, x1;\n\t"                                      \
        "add.rn.f32 de, de, x2;\n\t"                                      \
        "add.rn.f32 dq, y0, y1;\n\t"                                      \
        "add.rn.f32 dq, dq, y2;\n\t"                                      \
        "fma.rn.sat.f32 me, de, 0fF1800000, 0f72666667;\n\t"              \
        "fma.rn.sat.f32 mq, dq, 0fF1800000, 0f72666667;\n\t"              \
        "cvt.rn.bf16x2.f32 %0, mq, me;\n\t"                               \
        "}"                                                               \
        : "=r"(out)                                                       \
        : "l"(ci0), "l"(ci1), "l"(ci2), "l"(cj0), "l"(cj1), "l"(cj2))

#define MMA_BF16(d0, d1, d2, d3, a0, a1, a2, a3, b0, b1)                  \
    asm("mma.sync.aligned.m16n8k16.row.col.f32.bf16.bf16.f32 "            \
        "{%0,%1,%2,%3}, {%4,%5,%6,%7}, {%8,%9}, {%0,%1,%2,%3};"           \
        : "+f"(d0), "+f"(d1), "+f"(d2), "+f"(d3)                          \
        : "r"(a0), "r"(a1), "r"(a2), "r"(a3), "r"(b0), "r"(b1))

// ------- Kernel A: per-node MLP + exp weights + fused B-fragment build -------
__global__ void __launch_bounds__(32) prep_kernel(
    const float* __restrict__ x,
    const float* __restrict__ W1, const float* __restrict__ b1,
    const float* __restrict__ W2, const float* __restrict__ b2,
    const float* __restrict__ W3, const float* __restrict__ b3)
{
    __shared__ float sW1[DH * DIN], sb1[DH], sW2[DH * DH], sb2[DH],
                     sW3[DOUTK * DH], sb3[DOUTK];
    __shared__ float sx[32 * DIN];
    __shared__ unsigned short s_wvh[8][32];   // bf16 bits, [channel][j-local]
    const int t = threadIdx.x;
    {
        const float* xb = x + blockIdx.x * 32 * DIN;
        for (int k = t; k < 32 * DIN; k += 32) sx[k] = xb[k];
        for (int k = t; k < DH * DIN; k += 32) sW1[k] = W1[k];
        for (int k = t; k < DH * DH; k += 32) sW2[k] = W2[k];
        for (int k = t; k < DOUTK * DH; k += 32) sW3[k] = W3[k];
        if (t < DH) { sb1[t] = b1[t]; sb2[t] = b2[t]; }
        if (t < DOUTK) sb3[t] = b3[t];
    }
    __syncthreads();

    const int j = blockIdx.x * 32 + t;

    float xv[DIN];
#pragma unroll
    for (int k = 0; k < DIN; k++) xv[k] = sx[t * DIN + k];

    float h1[DH];
#pragma unroll
    for (int c = 0; c < DH; c++) {
        float z = sb1[c];
#pragma unroll
        for (int k = 0; k < DIN; k++) z += sW1[c * DIN + k] * xv[k];
        h1[c] = leaky(z);
    }
    float h2[DH];
#pragma unroll
    for (int c = 0; c < DH; c++) {
        float z = sb2[c];
#pragma unroll
        for (int k = 0; k < DH; k++) z += sW2[c * DH + k] * h1[k];
        h2[c] = leaky(z);
    }
    float h3[DOUTK];
#pragma unroll
    for (int c = 0; c < DOUTK; c++) {
        float z = sb3[c];
#pragma unroll
        for (int k = 0; k < DH; k++) z += sW3[c * DH + k] * h2[k];
        h3[c] = z;   // layer 3 is linear
    }

    float s = 0.0f;
#pragma unroll
    for (int k = 0; k < 8; k++) s += h3[DIN + k] * h3[DIN + 8 + k];
    const float w = expf(s);

    // bf16 aggregation channels (w*vals0..6, w)
#pragma unroll
    for (int c = 0; c < 8; c++) {
        const float v = (c < 7) ? w * h3[c] : w;
        const __nv_bfloat16 bf = __float2bfloat16(v);
        g_wvbf[c * NN + j] = bf;                       // for self-subtraction
        s_wvh[c][t] = __bfloat16_as_ushort(bf);
    }

    const int jp = j >> 1, hh = j & 1;
    g_cA[jp * 4 + 0 + hh] = -xv[0];
    g_cA[jp * 4 + 2 + hh] = -xv[1];
    g_cB[jp * 2 + hh]     = -xv[2];

    __syncthreads();

    // ---- fused B-fragment assembly: this CTA covers 2 K-steps of 16 j ----
    // m16n8k16 col B frag, lane (n0=lane/4, q=lane%4):
    //   v.x = {B[k0,n0],B[k0+1,n0]}, v.y = {B[k0+8,n0],B[k0+9,n0]}, k0=2q
    const int j0 = blockIdx.x * 32;
    const int kc = j0 >> 10;
    const int ks0 = (j0 & 1023) >> 4;
#pragma unroll
    for (int e = t; e < 64; e += 32) {
        const int lks = e >> 5, lane = e & 31;
        const int n0 = lane >> 2, q = lane & 3;
        const int bj = lks * 16 + 2 * q;
        uint2 v;
        v.x = (unsigned int)s_wvh[n0][bj] |
              ((unsigned int)s_wvh[n0][bj + 1] << 16);
        v.y = (unsigned int)s_wvh[n0][bj + 8] |
              ((unsigned int)s_wvh[n0][bj + 9] << 16);
        g_bfrag[kc * (KSTEPS * 32) + (ks0 + lks) * 32 + lane] = v;
    }
}

// ------- Kernel B: mask-gen + HMMA GEMM + last-CTA fused reduce/final -------
// CTA = (kchunk, mtile): 128 i x 1024 j; 8 warps, warp w -> 16 i rows.
__global__ void __launch_bounds__(256) pairmma_kernel(
    const float* __restrict__ x,
    const float* __restrict__ We, const float* __restrict__ be,
    const float* __restrict__ Wd, const float* __restrict__ bd,
    float* __restrict__ out)
{
    __shared__ uint2 s_bf[KSTEPS * 32];              // 16 KB B fragments
    __shared__ float4 s_cA[CJ / 2];                  //  8 KB
    __shared__ float2 s_cB[CJ / 2];                  //  4 KB
    __shared__ unsigned long long s_ci[128 * 3];     //  3 KB dup i-coords
    __shared__ float sWe[DH * 2 * DIN], sbe[DH], sWd[DIN * DH], sbd[DIN];
    __shared__ int s_last;

    const int tid = threadIdx.x, wid = tid >> 5, lane = tid & 31;
    const int kc = blockIdx.x, mt = blockIdx.y;
    const int g = lane >> 2, q = lane & 3;

    {
        const uint2* gbf = g_bfrag + kc * (KSTEPS * 32);
        for (int k = tid; k < KSTEPS * 32; k += 256) s_bf[k] = gbf[k];
        const float4* ga = reinterpret_cast<const float4*>(g_cA) + kc * (CJ / 2);
        for (int k = tid; k < CJ / 2; k += 256) s_cA[k] = ga[k];
        const float2* gb = reinterpret_cast<const float2*>(g_cB) + kc * (CJ / 2);
        for (int k = tid; k < CJ / 2; k += 256) s_cB[k] = gb[k];
        if (tid < 128) {
            const int i = mt * 128 + tid;
            const float c0 = x[i * DIN + 0];
            const float c1 = x[i * DIN + 1];
            const float c2 = x[i * DIN + 2];
            unsigned long long d0, d1, d2;
            asm("mov.b64 %0, {%1, %1};" : "=l"(d0) : "f"(c0));
            asm("mov.b64 %0, {%1, %1};" : "=l"(d1) : "f"(c1));
            asm("mov.b64 %0, {%1, %1};" : "=l"(d2) : "f"(c2));
            s_ci[tid * 3 + 0] = d0;
            s_ci[tid * 3 + 1] = d1;
            s_ci[tid * 3 + 2] = d2;
        }
    }
    __syncthreads();

    // this lane's two i-rows (m16n8k16 A layout), coords duplicated in f32x2
    const int r0 = wid * 16 + g;                     // row g of warp tile
    const unsigned long long ciA0 = s_ci[r0 * 3 + 0];
    const unsigned long long ciA1 = s_ci[r0 * 3 + 1];
    const unsigned long long ciA2 = s_ci[r0 * 3 + 2];
    const unsigned long long ciB0 = s_ci[(r0 + 8) * 3 + 0];
    const unsigned long long ciB1 = s_ci[(r0 + 8) * 3 + 1];
    const unsigned long long ciB2 = s_ci[(r0 + 8) * 3 + 2];

    // two accumulator groups (even/odd K-steps) break the HMMA dep chain
    float e0 = 0.f, e1 = 0.f, e2 = 0.f, e3 = 0.f;
    float o0 = 0.f, o1 = 0.f, o2 = 0.f, o3 = 0.f;

    const ulonglong2* cap = reinterpret_cast<const ulonglong2*>(s_cA);
    const unsigned long long* cbp =
        reinterpret_cast<const unsigned long long*>(s_cB);

#pragma unroll 8
    for (int ks = 0; ks < KSTEPS; ks++) {
        const int p0 = ks * 8 + q;                   // j-pair (2q) of this step
        const int p1 = p0 + 4;                       // j-pair (2q+8)
        const ulonglong2 ca0 = cap[p0];              // {-x0 pair, -x1 pair}
        const unsigned long long cb0 = cbp[p0];      // {-x2 pair}
        const ulonglong2 ca1 = cap[p1];
        const unsigned long long cb1 = cbp[p1];

        unsigned int a0, a1, a2, a3;
        MASKW(a0, ciA0, ciA1, ciA2, ca0.x, ca0.y, cb0);   // rows g,   cols k0
        MASKW(a1, ciB0, ciB1, ciB2, ca0.x, ca0.y, cb0);   // rows g+8, cols k0
        MASKW(a2, ciA0, ciA1, ciA2, ca1.x, ca1.y, cb1);   // rows g,   cols k0+8
        MASKW(a3, ciB0, ciB1, ciB2, ca1.x, ca1.y, cb1);   // rows g+8, cols k0+8

        const uint2 bf = s_bf[ks * 32 + lane];
        if (ks & 1) {
            MMA_BF16(o0, o1, o2, o3, a0, a1, a2, a3, bf.x, bf.y);
        } else {
            MMA_BF16(e0, e1, e2, e3, a0, a1, a2, a3, bf.x, bf.y);
        }
    }

    // D frag: lane holds rows {g, g+8}, channels {2q, 2q+1}
    const int i0 = mt * 128 + r0;
    *reinterpret_cast<float2*>(&g_part[kc][i0][2 * q]) =
        make_float2(e0 + o0, e1 + o1);
    *reinterpret_cast<float2*>(&g_part[kc][i0 + 8][2 * q]) =
        make_float2(e2 + o2, e3 + o3);

    // ---- last-CTA-per-mtile: fused chunk-reduce + final MLP ----
    __threadfence();
    __syncthreads();
    if (tid == 0) {
        const int old = atomicAdd(&g_cnt[mt], 1);
        s_last = (old == KC - 1) ? 1 : 0;
    }
    __syncthreads();
    if (!s_last) return;

    // stage tiny weights
    for (int k = tid; k < DH * 2 * DIN; k += 256) sWe[k] = We[k];
    if (tid < DIN * DH) sWd[tid] = Wd[tid];
    if (tid < DH) sbe[tid] = be[tid];
    if (tid < DIN) sbd[tid] = bd[tid];
    __syncthreads();

    if (tid < 128) {
        const int i = mt * 128 + tid;

        float a[8];
#pragma unroll
        for (int k = 0; k < 8; k++) a[k] = 0.0f;
#pragma unroll
        for (int c = 0; c < KC; c++) {
            const float4* p = reinterpret_cast<const float4*>(&g_part[c][i][0]);
            const float4 pa = p[0], pb = p[1];
            a[0] += pa.x; a[1] += pa.y; a[2] += pa.z; a[3] += pa.w;
            a[4] += pb.x; a[5] += pb.y; a[6] += pb.z; a[7] += pb.w;
        }
        // subtract self contribution exactly as the MMA added it (bf16-rounded)
#pragma unroll
        for (int c = 0; c < 8; c++)
            a[c] -= __bfloat162float(g_wvbf[c * NN + i]);
        const float inv = 1.0f / fmaxf(a[7], 1e-30f);

        float agg[DIN];
#pragma unroll
        for (int k = 0; k < DIN; k++) agg[k] = a[k] * inv;

        float xv[DIN];
#pragma unroll
        for (int k = 0; k < DIN; k++) xv[k] = x[i * DIN + k];

        float codes[DH];
#pragma unroll
        for (int c = 0; c < DH; c++) {
            float z = sbe[c];
#pragma unroll
            for (int k = 0; k < DIN; k++) z += sWe[c * (2 * DIN) + k] * xv[k];
#pragma unroll
            for (int k = 0; k < DIN; k++)
                z += sWe[c * (2 * DIN) + DIN + k] * agg[k];
            codes[c] = leaky(z);
        }
#pragma unroll
        for (int d = 0; d < DIN; d++) {
            float z = sbd[d];
#pragma unroll
            for (int c = 0; c < DH; c++) z += sWd[d * DH + c] * codes[c];
            out[i * DIN + d] = z;
        }
    }
    if (tid == 0) g_cnt[mt] = 0;   // self-reset for next graph replay
}

// ---------------- launch ----------------
extern "C" void kernel_launch(void* const* d_in, const int* in_sizes, int n_in,
                              void* d_out, int out_size)
{
    const float* x  = (const float*)d_in[0];
    const float* W1 = (const float*)d_in[1];
    const float* b1 = (const float*)d_in[2];
    const float* W2 = (const float*)d_in[3];
    const float* b2 = (const float*)d_in[4];
    const float* W3 = (const float*)d_in[5];
    const float* b3 = (const float*)d_in[6];
    const float* We = (const float*)d_in[7];
    const float* be = (const float*)d_in[8];
    const float* Wd = (const float*)d_in[9];
    const float* bd = (const float*)d_in[10];
    float* out = (float*)d_out;

    prep_kernel<<<NN / 32, 32>>>(x, W1, b1, W2, b2, W3, b3);
    dim3 grid(KC, MT);
    pairmma_kernel<<<grid, 256>>>(x, We, be, Wd, bd, out);
}

// round 14
// speedup vs baseline: 2.1014x; 1.0263x over previous
#include <cuda_runtime.h>
#include <cuda_bf16.h>

#define NN 8192
#define DIN 7
#define DH 8
#define DOUTK 23
#define KC 8                  /* K-chunks (grid.x), 1024 j each */
#define MT 128                /* M-tiles of 64 i  (grid.y)      */
#define CJ 1024               /* j per chunk                    */
#define KSTEPS (CJ / 16)      /* 64 mma K-steps per chunk       */

// -------- device scratch (no allocations allowed) --------
__device__ float g_cA[(NN / 2) * 4];         // per j-pair: {-x0a,-x0b,-x1a,-x1b}
__device__ float g_cB[(NN / 2) * 2];         // per j-pair: {-x2a,-x2b}
__device__ __nv_bfloat16 g_wvbf[8 * NN];     // rows 0-6 = w*vals, row 7 = w
__device__ uint2 g_bfrag[KC * KSTEPS * 32];  // preassembled B fragments
__device__ float g_part[KC][NN][8];          // K-chunk partial accumulators
__device__ int g_cnt[MT];                    // per-mtile counters (0-init, self-reset)

__device__ __forceinline__ float leaky(float v) {
    return v >= 0.0f ? v : 0.01f * v;
}

// one bf16x2 mask word: lanes of f32x2 = (j even, j odd)
// d = (|ci0-cj0| + |ci1-cj1|) + |ci2-cj2|  -- reference fp32 order, j pre-negated.
// Threshold via FFMA.SAT: m = sat(d*(-2^100) + C'*2^100), C' = nextafter(3.6f).
// Product exact (pow2 scale) => m>0 <=> d <= 3.6f bit-exactly; positives
// saturate to exactly 1.0. sat output is 0.0/1.0 => bf16 = high 16 bits,
// packed with PRMT (ALU pipe) instead of CVT: lo16=me[31:16], hi16=mq[31:16].
#define MASKW(out, ci0, ci1, ci2, cj0, cj1, cj2)                          \
    asm("{\n\t"                                                           \
        ".reg .b64 u0,u1,u2;\n\t"                                         \
        ".reg .f32 x0,x1,x2,y0,y1,y2,de,dq,me,mq;\n\t"                    \
        ".reg .b32 ime,imq;\n\t"                                          \
        "add.rn.f32x2 u0, %1, %4;\n\t"                                    \
        "add.rn.f32x2 u1, %2, %5;\n\t"                                    \
        "add.rn.f32x2 u2, %3, %6;\n\t"                                    \
        "mov.b64 {x0,y0}, u0;\n\t"                                        \
        "mov.b64 {x1,y1}, u1;\n\t"                                        \
        "mov.b64 {x2,y2}, u2;\n\t"                                        \
        "abs.f32 x0, x0;\n\t"                                             \
        "abs.f32 x1, x1;\n\t"                                             \
        "abs.f32 x2, x2;\n\t"                                             \
        "abs.f32 y0, y0;\n\t"                                             \
        "abs.f32 y1, y1;\n\t"                                             \
        "abs.f32 y2, y2;\n\t"                                             \
        "add.rn.f32 de, x0, x1;\n\t"                                      \
        "add.rn.f32 de, de, x2;\n\t"                                      \
        "add.rn.f32 dq, y0, y1;\n\t"                                      \
        "add.rn.f32 dq, dq, y2;\n\t"                                      \
        "fma.rn.sat.f32 me, de, 0fF1800000, 0f72666667;\n\t"              \
        "fma.rn.sat.f32 mq, dq, 0fF1800000, 0f72666667;\n\t"              \
        "mov.b32 ime, me;\n\t"                                            \
        "mov.b32 imq, mq;\n\t"                                            \
        "prmt.b32 %0, ime, imq, 0x7632;\n\t"                              \
        "}"                                                               \
        : "=r"(out)                                                       \
        : "l"(ci0), "l"(ci1), "l"(ci2), "l"(cj0), "l"(cj1), "l"(cj2))

#define MMA_BF16(d0, d1, d2, d3, a0, a1, a2, a3, b0, b1)                  \
    asm("mma.sync.aligned.m16n8k16.row.col.f32.bf16.bf16.f32 "            \
        "{%0,%1,%2,%3}, {%4,%5,%6,%7}, {%8,%9}, {%0,%1,%2,%3};"           \
        : "+f"(d0), "+f"(d1), "+f"(d2), "+f"(d3)                          \
        : "r"(a0), "r"(a1), "r"(a2), "r"(a3), "r"(b0), "r"(b1))

// ------- Kernel A: per-node MLP + exp weights + fused B-fragment build -------
__global__ void __launch_bounds__(32) prep_kernel(
    const float* __restrict__ x,
    const float* __restrict__ W1, const float* __restrict__ b1,
    const float* __restrict__ W2, const float* __restrict__ b2,
    const float* __restrict__ W3, const float* __restrict__ b3)
{
    __shared__ float sW1[DH * DIN], sb1[DH], sW2[DH * DH], sb2[DH],
                     sW3[DOUTK * DH], sb3[DOUTK];
    __shared__ float sx[32 * DIN];
    __shared__ unsigned short s_wvh[8][32];   // bf16 bits, [channel][j-local]
    const int t = threadIdx.x;
    {
        const float* xb = x + blockIdx.x * 32 * DIN;
        for (int k = t; k < 32 * DIN; k += 32) sx[k] = xb[k];
        for (int k = t; k < DH * DIN; k += 32) sW1[k] = W1[k];
        for (int k = t; k < DH * DH; k += 32) sW2[k] = W2[k];
        for (int k = t; k < DOUTK * DH; k += 32) sW3[k] = W3[k];
        if (t < DH) { sb1[t] = b1[t]; sb2[t] = b2[t]; }
        if (t < DOUTK) sb3[t] = b3[t];
    }
    __syncthreads();

    const int j = blockIdx.x * 32 + t;

    float xv[DIN];
#pragma unroll
    for (int k = 0; k < DIN; k++) xv[k] = sx[t * DIN + k];

    float h1[DH];
#pragma unroll
    for (int c = 0; c < DH; c++) {
        float z = sb1[c];
#pragma unroll
        for (int k = 0; k < DIN; k++) z += sW1[c * DIN + k] * xv[k];
        h1[c] = leaky(z);
    }
    float h2[DH];
#pragma unroll
    for (int c = 0; c < DH; c++) {
        float z = sb2[c];
#pragma unroll
        for (int k = 0; k < DH; k++) z += sW2[c * DH + k] * h1[k];
        h2[c] = leaky(z);
    }
    float h3[DOUTK];
#pragma unroll
    for (int c = 0; c < DOUTK; c++) {
        float z = sb3[c];
#pragma unroll
        for (int k = 0; k < DH; k++) z += sW3[c * DH + k] * h2[k];
        h3[c] = z;   // layer 3 is linear
    }

    float s = 0.0f;
#pragma unroll
    for (int k = 0; k < 8; k++) s += h3[DIN + k] * h3[DIN + 8 + k];
    const float w = expf(s);

    // bf16 aggregation channels (w*vals0..6, w)
#pragma unroll
    for (int c = 0; c < 8; c++) {
        const float v = (c < 7) ? w * h3[c] : w;
        const __nv_bfloat16 bf = __float2bfloat16(v);
        g_wvbf[c * NN + j] = bf;                       // for self-subtraction
        s_wvh[c][t] = __bfloat16_as_ushort(bf);
    }

    const int jp = j >> 1, hh = j & 1;
    g_cA[jp * 4 + 0 + hh] = -xv[0];
    g_cA[jp * 4 + 2 + hh] = -xv[1];
    g_cB[jp * 2 + hh]     = -xv[2];

    __syncthreads();

    // ---- fused B-fragment assembly: this CTA covers 2 K-steps of 16 j ----
    // m16n8k16 col B frag, lane (n0=lane/4, q=lane%4):
    //   v.x = {B[k0,n0],B[k0+1,n0]}, v.y = {B[k0+8,n0],B[k0+9,n0]}, k0=2q
    const int j0 = blockIdx.x * 32;
    const int kc = j0 >> 10;
    const int ks0 = (j0 & 1023) >> 4;
#pragma unroll
    for (int e = t; e < 64; e += 32) {
        const int lks = e >> 5, lane = e & 31;
        const int n0 = lane >> 2, q = lane & 3;
        const int bj = lks * 16 + 2 * q;
        uint2 v;
        v.x = (unsigned int)s_wvh[n0][bj] |
              ((unsigned int)s_wvh[n0][bj + 1] << 16);
        v.y = (unsigned int)s_wvh[n0][bj + 8] |
              ((unsigned int)s_wvh[n0][bj + 9] << 16);
        g_bfrag[kc * (KSTEPS * 32) + (ks0 + lks) * 32 + lane] = v;
    }
}

// ------- Kernel B: mask-gen + HMMA GEMM + last-CTA fused reduce/final -------
// CTA = (kchunk, mtile): 64 i x 1024 j; 4 warps, warp w -> 16 i rows.
__global__ void __launch_bounds__(128) pairmma_kernel(
    const float* __restrict__ x,
    const float* __restrict__ We, const float* __restrict__ be,
    const float* __restrict__ Wd, const float* __restrict__ bd,
    float* __restrict__ out)
{
    __shared__ uint2 s_bf[KSTEPS * 32];              // 16 KB B fragments
    __shared__ float4 s_cA[CJ / 2];                  //  8 KB
    __shared__ float2 s_cB[CJ / 2];                  //  4 KB
    __shared__ unsigned long long s_ci[64 * 3];      //  1.5 KB dup i-coords
    __shared__ float sWe[DH * 2 * DIN], sbe[DH], sWd[DIN * DH], sbd[DIN];
    __shared__ int s_last;

    const int tid = threadIdx.x, wid = tid >> 5, lane = tid & 31;
    const int kc = blockIdx.x, mt = blockIdx.y;
    const int g = lane >> 2, q = lane & 3;

    {
        const uint4* gbf = reinterpret_cast<const uint4*>(g_bfrag + kc * (KSTEPS * 32));
        uint4* sbf4 = reinterpret_cast<uint4*>(s_bf);
        for (int k = tid; k < KSTEPS * 16; k += 128) sbf4[k] = gbf[k];
        const float4* ga = reinterpret_cast<const float4*>(g_cA) + kc * (CJ / 2);
        for (int k = tid; k < CJ / 2; k += 128) s_cA[k] = ga[k];
        const float2* gb = reinterpret_cast<const float2*>(g_cB) + kc * (CJ / 2);
        for (int k = tid; k < CJ / 2; k += 128) s_cB[k] = gb[k];
        if (tid < 64) {
            const int i = mt * 64 + tid;
            const float c0 = x[i * DIN + 0];
            const float c1 = x[i * DIN + 1];
            const float c2 = x[i * DIN + 2];
            unsigned long long d0, d1, d2;
            asm("mov.b64 %0, {%1, %1};" : "=l"(d0) : "f"(c0));
            asm("mov.b64 %0, {%1, %1};" : "=l"(d1) : "f"(c1));
            asm("mov.b64 %0, {%1, %1};" : "=l"(d2) : "f"(c2));
            s_ci[tid * 3 + 0] = d0;
            s_ci[tid * 3 + 1] = d1;
            s_ci[tid * 3 + 2] = d2;
        }
    }
    __syncthreads();

    // this lane's two i-rows (m16n8k16 A layout), coords duplicated in f32x2
    const int r0 = wid * 16 + g;                     // row g of warp tile
    const unsigned long long ciA0 = s_ci[r0 * 3 + 0];
    const unsigned long long ciA1 = s_ci[r0 * 3 + 1];
    const unsigned long long ciA2 = s_ci[r0 * 3 + 2];
    const unsigned long long ciB0 = s_ci[(r0 + 8) * 3 + 0];
    const unsigned long long ciB1 = s_ci[(r0 + 8) * 3 + 1];
    const unsigned long long ciB2 = s_ci[(r0 + 8) * 3 + 2];

    // two accumulator groups (even/odd K-steps) break the HMMA dep chain
    float e0 = 0.f, e1 = 0.f, e2 = 0.f, e3 = 0.f;
    float o0 = 0.f, o1 = 0.f, o2 = 0.f, o3 = 0.f;

    const ulonglong2* cap = reinterpret_cast<const ulonglong2*>(s_cA);
    const unsigned long long* cbp =
        reinterpret_cast<const unsigned long long*>(s_cB);

#pragma unroll 8
    for (int ks = 0; ks < KSTEPS; ks++) {
        const int p0 = ks * 8 + q;                   // j-pair (2q) of this step
        const int p1 = p0 + 4;                       // j-pair (2q+8)
        const ulonglong2 ca0 = cap[p0];              // {-x0 pair, -x1 pair}
        const unsigned long long cb0 = cbp[p0];      // {-x2 pair}
        const ulonglong2 ca1 = cap[p1];
        const unsigned long long cb1 = cbp[p1];

        unsigned int a0, a1, a2, a3;
        MASKW(a0, ciA0, ciA1, ciA2, ca0.x, ca0.y, cb0);   // rows g,   cols k0
        MASKW(a1, ciB0, ciB1, ciB2, ca0.x, ca0.y, cb0);   // rows g+8, cols k0
        MASKW(a2, ciA0, ciA1, ciA2, ca1.x, ca1.y, cb1);   // rows g,   cols k0+8
        MASKW(a3, ciB0, ciB1, ciB2, ca1.x, ca1.y, cb1);   // rows g+8, cols k0+8

        const uint2 bf = s_bf[ks * 32 + lane];
        if (ks & 1) {
            MMA_BF16(o0, o1, o2, o3, a0, a1, a2, a3, bf.x, bf.y);
        } else {
            MMA_BF16(e0, e1, e2, e3, a0, a1, a2, a3, bf.x, bf.y);
        }
    }

    // D frag: lane holds rows {g, g+8}, channels {2q, 2q+1}
    const int i0 = mt * 64 + r0;
    *reinterpret_cast<float2*>(&g_part[kc][i0][2 * q]) =
        make_float2(e0 + o0, e1 + o1);
    *reinterpret_cast<float2*>(&g_part[kc][i0 + 8][2 * q]) =
        make_float2(e2 + o2, e3 + o3);

    // ---- last-CTA-per-mtile: fused chunk-reduce + final MLP ----
    __threadfence();
    __syncthreads();
    if (tid == 0) {
        const int old = atomicAdd(&g_cnt[mt], 1);
        s_last = (old == KC - 1) ? 1 : 0;
    }
    __syncthreads();
    if (!s_last) return;

    // stage tiny weights
    for (int k = tid; k < DH * 2 * DIN; k += 128) sWe[k] = We[k];
    if (tid < DIN * DH) sWd[tid] = Wd[tid];
    if (tid < DH) sbe[tid] = be[tid];
    if (tid < DIN) sbd[tid] = bd[tid];
    __syncthreads();

    if (tid < 64) {
        const int i = mt * 64 + tid;

        float a[8];
#pragma unroll
        for (int k = 0; k < 8; k++) a[k] = 0.0f;
#pragma unroll
        for (int c = 0; c < KC; c++) {
            const float4* p = reinterpret_cast<const float4*>(&g_part[c][i][0]);
            const float4 pa = p[0], pb = p[1];
            a[0] += pa.x; a[1] += pa.y; a[2] += pa.z; a[3] += pa.w;
            a[4] += pb.x; a[5] += pb.y; a[6] += pb.z; a[7] += pb.w;
        }
        // subtract self contribution exactly as the MMA added it (bf16-rounded)
#pragma unroll
        for (int c = 0; c < 8; c++)
            a[c] -= __bfloat162float(g_wvbf[c * NN + i]);
        const float inv = 1.0f / fmaxf(a[7], 1e-30f);

        float agg[DIN];
#pragma unroll
        for (int k = 0; k < DIN; k++) agg[k] = a[k] * inv;

        float xv[DIN];
#pragma unroll
        for (int k = 0; k < DIN; k++) xv[k] = x[i * DIN + k];

        float codes[DH];
#pragma unroll
        for (int c = 0; c < DH; c++) {
            float z = sbe[c];
#pragma unroll
            for (int k = 0; k < DIN; k++) z += sWe[c * (2 * DIN) + k] * xv[k];
#pragma unroll
            for (int k = 0; k < DIN; k++)
                z += sWe[c * (2 * DIN) + DIN + k] * agg[k];
            codes[c] = leaky(z);
        }
#pragma unroll
        for (int d = 0; d < DIN; d++) {
            float z = sbd[d];
#pragma unroll
            for (int c = 0; c < DH; c++) z += sWd[d * DH + c] * codes[c];
            out[i * DIN + d] = z;
        }
    }
    if (tid == 0) g_cnt[mt] = 0;   // self-reset for next graph replay
}

// ---------------- launch ----------------
extern "C" void kernel_launch(void* const* d_in, const int* in_sizes, int n_in,
                              void* d_out, int out_size)
{
    const float* x  = (const float*)d_in[0];
    const float* W1 = (const float*)d_in[1];
    const float* b1 = (const float*)d_in[2];
    const float* W2 = (const float*)d_in[3];
    const float* b2 = (const float*)d_in[4];
    const float* W3 = (const float*)d_in[5];
    const float* b3 = (const float*)d_in[6];
    const float* We = (const float*)d_in[7];
    const float* be = (const float*)d_in[8];
    const float* Wd = (const float*)d_in[9];
    const float* bd = (const float*)d_in[10];
    float* out = (float*)d_out;

    prep_kernel<<<NN / 32, 32>>>(x, W1, b1, W2, b2, W3, b3);
    dim3 grid(KC, MT);
    pairmma_kernel<<<grid, 128>>>(x, We, be, Wd, bd, out);
}

// round 15
// speedup vs baseline: 2.3770x; 1.1311x over previous
#include <cuda_runtime.h>
#include <cuda_bf16.h>

#define NN 8192
#define DIN 7
#define DH 8
#define DOUTK 23
#define KC 16                 /* K-chunks (grid.x), 512 j each  */
#define MT 128                /* M-tiles of 64 i  (grid.y)      */
#define CJ 512                /* j per chunk                    */
#define KSTEPS (CJ / 16)      /* 32 mma K-steps per chunk       */

// -------- device scratch (no allocations allowed) --------
__device__ float g_cA[(NN / 2) * 4];         // per j-pair: {-x0a,-x0b,-x1a,-x1b}
__device__ float4 g_cC[KC * KSTEPS * 4];     // per (kc,ks,q): {-x2 p0 pair, -x2 p1 pair}
__device__ __nv_bfloat16 g_wvbf[8 * NN];     // rows 0-6 = w*vals, row 7 = w
__device__ uint2 g_bfrag[KC * KSTEPS * 32];  // preassembled B fragments
__device__ float g_part[KC][NN][8];          // K-chunk partial accumulators
__device__ int g_cnt[MT];                    // per-mtile counters (0-init, self-reset)

__device__ __forceinline__ float leaky(float v) {
    return v >= 0.0f ? v : 0.01f * v;
}

// one bf16x2 mask word: lanes of f32x2 = (j even, j odd)
// d = (|ci0-cj0| + |ci1-cj1|) + |ci2-cj2|  -- reference fp32 order, j pre-negated.
// Threshold via FFMA.SAT: m = sat(d*(-2^100) + C'*2^100), C' = nextafter(3.6f).
// Product exact (pow2 scale) => m>0 <=> d <= 3.6f bit-exactly; positives
// saturate to exactly 1.0. sat output is 0.0/1.0 => bf16 = high 16 bits,
// packed with PRMT (ALU pipe): lo16=me[31:16], hi16=mq[31:16].
#define MASKW(out, ci0, ci1, ci2, cj0, cj1, cj2)                          \
    asm("{\n\t"                                                           \
        ".reg .b64 u0,u1,u2;\n\t"                                         \
        ".reg .f32 x0,x1,x2,y0,y1,y2,de,dq,me,mq;\n\t"                    \
        ".reg .b32 ime,imq;\n\t"                                          \
        "add.rn.f32x2 u0, %1, %4;\n\t"                                    \
        "add.rn.f32x2 u1, %2, %5;\n\t"                                    \
        "add.rn.f32x2 u2, %3, %6;\n\t"                                    \
        "mov.b64 {x0,y0}, u0;\n\t"                                        \
        "mov.b64 {x1,y1}, u1;\n\t"                                        \
        "mov.b64 {x2,y2}, u2;\n\t"                                        \
        "abs.f32 x0, x0;\n\t"                                             \
        "abs.f32 x1, x1;\n\t"                                             \
        "abs.f32 x2, x2;\n\t"                                             \
        "abs.f32 y0, y0;\n\t"                                             \
        "abs.f32 y1, y1;\n\t"                                             \
        "abs.f32 y2, y2;\n\t"                                             \
        "add.rn.f32 de, x0, x1;\n\t"                                      \
        "add.rn.f32 de, de, x2;\n\t"                                      \
        "add.rn.f32 dq, y0, y1;\n\t"                                      \
        "add.rn.f32 dq, dq, y2;\n\t"                                      \
        "fma.rn.sat.f32 me, de, 0fF1800000, 0f72666667;\n\t"              \
        "fma.rn.sat.f32 mq, dq, 0fF1800000, 0f72666667;\n\t"              \
        "mov.b32 ime, me;\n\t"                                            \
        "mov.b32 imq, mq;\n\t"                                            \
        "prmt.b32 %0, ime, imq, 0x7632;\n\t"                              \
        "}"                                                               \
        : "=r"(out)                                                       \
        : "l"(ci0), "l"(ci1), "l"(ci2), "l"(cj0), "l"(cj1), "l"(cj2))

#define MMA_BF16(d0, d1, d2, d3, a0, a1, a2, a3, b0, b1)                  \
    asm("mma.sync.aligned.m16n8k16.row.col.f32.bf16.bf16.f32 "            \
        "{%0,%1,%2,%3}, {%4,%5,%6,%7}, {%8,%9}, {%0,%1,%2,%3};"           \
        : "+f"(d0), "+f"(d1), "+f"(d2), "+f"(d3)                          \
        : "r"(a0), "r"(a1), "r"(a2), "r"(a3), "r"(b0), "r"(b1))

// ------- Kernel A: per-node MLP + exp weights + fused fragment build -------
__global__ void __launch_bounds__(32) prep_kernel(
    const float* __restrict__ x,
    const float* __restrict__ W1, const float* __restrict__ b1,
    const float* __restrict__ W2, const float* __restrict__ b2,
    const float* __restrict__ W3, const float* __restrict__ b3)
{
    __shared__ float sW1[DH * DIN], sb1[DH], sW2[DH * DH], sb2[DH],
                     sW3[DOUTK * DH], sb3[DOUTK];
    __shared__ float sx[32 * DIN];
    __shared__ unsigned short s_wvh[8][32];   // bf16 bits, [channel][j-local]
    __shared__ float s_x2[32];                // -x2 per local j
    const int t = threadIdx.x;
    {
        const float* xb = x + blockIdx.x * 32 * DIN;
        for (int k = t; k < 32 * DIN; k += 32) sx[k] = xb[k];
        for (int k = t; k < DH * DIN; k += 32) sW1[k] = W1[k];
        for (int k = t; k < DH * DH; k += 32) sW2[k] = W2[k];
        for (int k = t; k < DOUTK * DH; k += 32) sW3[k] = W3[k];
        if (t < DH) { sb1[t] = b1[t]; sb2[t] = b2[t]; }
        if (t < DOUTK) sb3[t] = b3[t];
    }
    __syncthreads();

    const int j = blockIdx.x * 32 + t;

    float xv[DIN];
#pragma unroll
    for (int k = 0; k < DIN; k++) xv[k] = sx[t * DIN + k];

    float h1[DH];
#pragma unroll
    for (int c = 0; c < DH; c++) {
        float z = sb1[c];
#pragma unroll
        for (int k = 0; k < DIN; k++) z += sW1[c * DIN + k] * xv[k];
        h1[c] = leaky(z);
    }
    float h2[DH];
#pragma unroll
    for (int c = 0; c < DH; c++) {
        float z = sb2[c];
#pragma unroll
        for (int k = 0; k < DH; k++) z += sW2[c * DH + k] * h1[k];
        h2[c] = leaky(z);
    }
    float h3[DOUTK];
#pragma unroll
    for (int c = 0; c < DOUTK; c++) {
        float z = sb3[c];
#pragma unroll
        for (int k = 0; k < DH; k++) z += sW3[c * DH + k] * h2[k];
        h3[c] = z;   // layer 3 is linear
    }

    float s = 0.0f;
#pragma unroll
    for (int k = 0; k < 8; k++) s += h3[DIN + k] * h3[DIN + 8 + k];
    const float w = expf(s);

    // bf16 aggregation channels (w*vals0..6, w)
#pragma unroll
    for (int c = 0; c < 8; c++) {
        const float v = (c < 7) ? w * h3[c] : w;
        const __nv_bfloat16 bf = __float2bfloat16(v);
        g_wvbf[c * NN + j] = bf;                       // for self-subtraction
        s_wvh[c][t] = __bfloat16_as_ushort(bf);
    }

    const int jp = j >> 1, hh = j & 1;
    g_cA[jp * 4 + 0 + hh] = -xv[0];
    g_cA[jp * 4 + 2 + hh] = -xv[1];
    s_x2[t] = -xv[2];

    __syncthreads();

    // ---- fused fragment assembly: this CTA covers 2 K-steps of 16 j ----
    const int j0 = blockIdx.x * 32;
    const int kc = j0 >> 9;                 // CJ = 512
    const int ks0 = (j0 & 511) >> 4;

    // B fragments: m16n8k16 col B, lane (n0=lane/4, q=lane%4):
    //   v.x = {B[k0,n0],B[k0+1,n0]}, v.y = {B[k0+8,n0],B[k0+9,n0]}, k0=2q
#pragma unroll
    for (int e = t; e < 64; e += 32) {
        const int lks = e >> 5, lane = e & 31;
        const int n0 = lane >> 2, q = lane & 3;
        const int bj = lks * 16 + 2 * q;
        uint2 v;
        v.x = (unsigned int)s_wvh[n0][bj] |
              ((unsigned int)s_wvh[n0][bj + 1] << 16);
        v.y = (unsigned int)s_wvh[n0][bj + 8] |
              ((unsigned int)s_wvh[n0][bj + 9] << 16);
        g_bfrag[kc * (KSTEPS * 32) + (ks0 + lks) * 32 + lane] = v;
    }

    // packed x2 table: entry (ks, q) = {-x2 pair p0, -x2 pair p1},
    // p0 = ks*8+q, p1 = p0+4 (local pair index = global - ks0*8)
    if (t < 8) {
        const int lks = t >> 2, q = t & 3;
        const int lp0 = lks * 8 + q, lp1 = lp0 + 4;
        g_cC[kc * (KSTEPS * 4) + (ks0 + lks) * 4 + q] =
            make_float4(s_x2[2 * lp0], s_x2[2 * lp0 + 1],
                        s_x2[2 * lp1], s_x2[2 * lp1 + 1]);
    }
}

// ------- Kernel B: mask-gen + HMMA GEMM + last-CTA fused reduce/final -------
// CTA = (kchunk, mtile): 64 i x 512 j; 4 warps, warp w -> 16 i rows.
__global__ void __launch_bounds__(128, 8) pairmma_kernel(
    const float* __restrict__ x,
    const float* __restrict__ We, const float* __restrict__ be,
    const float* __restrict__ Wd, const float* __restrict__ bd,
    float* __restrict__ out)
{
    __shared__ uint2 s_bf[KSTEPS * 32];              //  8 KB B fragments
    __shared__ float4 s_cA[CJ / 2];                  //  4 KB
    __shared__ float4 s_cC[KSTEPS * 4];              //  2 KB packed x2
    __shared__ unsigned long long s_ci[64 * 3];      //  1.5 KB dup i-coords
    __shared__ float sWe[DH * 2 * DIN], sbe[DH], sWd[DIN * DH], sbd[DIN];
    __shared__ int s_last;

    const int tid = threadIdx.x, wid = tid >> 5, lane = tid & 31;
    const int kc = blockIdx.x, mt = blockIdx.y;
    const int g = lane >> 2, q = lane & 3;

    {
        const uint4* gbf = reinterpret_cast<const uint4*>(g_bfrag + kc * (KSTEPS * 32));
        uint4* sbf4 = reinterpret_cast<uint4*>(s_bf);
        for (int k = tid; k < KSTEPS * 16; k += 128) sbf4[k] = gbf[k];
        const float4* ga = reinterpret_cast<const float4*>(g_cA) + kc * (CJ / 2);
        for (int k = tid; k < CJ / 2; k += 128) s_cA[k] = ga[k];
        if (tid < KSTEPS * 4) s_cC[tid] = g_cC[kc * (KSTEPS * 4) + tid];
        if (tid < 64) {
            const int i = mt * 64 + tid;
            const float c0 = x[i * DIN + 0];
            const float c1 = x[i * DIN + 1];
            const float c2 = x[i * DIN + 2];
            unsigned long long d0, d1, d2;
            asm("mov.b64 %0, {%1, %1};" : "=l"(d0) : "f"(c0));
            asm("mov.b64 %0, {%1, %1};" : "=l"(d1) : "f"(c1));
            asm("mov.b64 %0, {%1, %1};" : "=l"(d2) : "f"(c2));
            s_ci[tid * 3 + 0] = d0;
            s_ci[tid * 3 + 1] = d1;
            s_ci[tid * 3 + 2] = d2;
        }
    }
    __syncthreads();

    // this lane's two i-rows (m16n8k16 A layout), coords duplicated in f32x2
    const int r0 = wid * 16 + g;                     // row g of warp tile
    const unsigned long long ciA0 = s_ci[r0 * 3 + 0];
    const unsigned long long ciA1 = s_ci[r0 * 3 + 1];
    const unsigned long long ciA2 = s_ci[r0 * 3 + 2];
    const unsigned long long ciB0 = s_ci[(r0 + 8) * 3 + 0];
    const unsigned long long ciB1 = s_ci[(r0 + 8) * 3 + 1];
    const unsigned long long ciB2 = s_ci[(r0 + 8) * 3 + 2];

    // two accumulator groups (even/odd K-steps) break the HMMA dep chain
    float e0 = 0.f, e1 = 0.f, e2 = 0.f, e3 = 0.f;
    float o0 = 0.f, o1 = 0.f, o2 = 0.f, o3 = 0.f;

    const ulonglong2* cap = reinterpret_cast<const ulonglong2*>(s_cA);
    const ulonglong2* ccp = reinterpret_cast<const ulonglong2*>(s_cC);

#pragma unroll 8
    for (int ks = 0; ks < KSTEPS; ks++) {
        const int p0 = ks * 8 + q;                   // j-pair (2q) of this step
        const int p1 = p0 + 4;                       // j-pair (2q+8)
        const ulonglong2 ca0 = cap[p0];              // {-x0 pair, -x1 pair}
        const ulonglong2 ca1 = cap[p1];
        const ulonglong2 cc = ccp[ks * 4 + q];       // {-x2 p0 pair, -x2 p1 pair}

        unsigned int a0, a1, a2, a3;
        MASKW(a0, ciA0, ciA1, ciA2, ca0.x, ca0.y, cc.x);  // rows g,   cols k0
        MASKW(a1, ciB0, ciB1, ciB2, ca0.x, ca0.y, cc.x);  // rows g+8, cols k0
        MASKW(a2, ciA0, ciA1, ciA2, ca1.x, ca1.y, cc.y);  // rows g,   cols k0+8
        MASKW(a3, ciB0, ciB1, ciB2, ca1.x, ca1.y, cc.y);  // rows g+8, cols k0+8

        const uint2 bf = s_bf[ks * 32 + lane];
        if (ks & 1) {
            MMA_BF16(o0, o1, o2, o3, a0, a1, a2, a3, bf.x, bf.y);
        } else {
            MMA_BF16(e0, e1, e2, e3, a0, a1, a2, a3, bf.x, bf.y);
        }
    }

    // D frag: lane holds rows {g, g+8}, channels {2q, 2q+1}
    const int i0 = mt * 64 + r0;
    *reinterpret_cast<float2*>(&g_part[kc][i0][2 * q]) =
        make_float2(e0 + o0, e1 + o1);
    *reinterpret_cast<float2*>(&g_part[kc][i0 + 8][2 * q]) =
        make_float2(e2 + o2, e3 + o3);

    // ---- last-CTA-per-mtile: fused chunk-reduce + final MLP ----
    __threadfence();
    __syncthreads();
    if (tid == 0) {
        const int old = atomicAdd(&g_cnt[mt], 1);
        s_last = (old == KC - 1) ? 1 : 0;
    }
    __syncthreads();
    if (!s_last) return;

    // stage tiny weights
    for (int k = tid; k < DH * 2 * DIN; k += 128) sWe[k] = We[k];
    if (tid < DIN * DH) sWd[tid] = Wd[tid];
    if (tid < DH) sbe[tid] = be[tid];
    if (tid < DIN) sbd[tid] = bd[tid];
    __syncthreads();

    if (tid < 64) {
        const int i = mt * 64 + tid;

        float a[8];
#pragma unroll
        for (int k = 0; k < 8; k++) a[k] = 0.0f;
#pragma unroll
        for (int c = 0; c < KC; c++) {
            const float4* p = reinterpret_cast<const float4*>(&g_part[c][i][0]);
            const float4 pa = p[0], pb = p[1];
            a[0] += pa.x; a[1] += pa.y; a[2] += pa.z; a[3] += pa.w;
            a[4] += pb.x; a[5] += pb.y; a[6] += pb.z; a[7] += pb.w;
        }
        // subtract self contribution exactly as the MMA added it (bf16-rounded)
#pragma unroll
        for (int c = 0; c < 8; c++)
            a[c] -= __bfloat162float(g_wvbf[c * NN + i]);
        const float inv = 1.0f / fmaxf(a[7], 1e-30f);

        float agg[DIN];
#pragma unroll
        for (int k = 0; k < DIN; k++) agg[k] = a[k] * inv;

        float xv[DIN];
#pragma unroll
        for (int k = 0; k < DIN; k++) xv[k] = x[i * DIN + k];

        float codes[DH];
#pragma unroll
        for (int c = 0; c < DH; c++) {
            float z = sbe[c];
#pragma unroll
            for (int k = 0; k < DIN; k++) z += sWe[c * (2 * DIN) + k] * xv[k];
#pragma unroll
            for (int k = 0; k < DIN; k++)
                z += sWe[c * (2 * DIN) + DIN + k] * agg[k];
            codes[c] = leaky(z);
        }
#pragma unroll
        for (int d = 0; d < DIN; d++) {
            float z = sbd[d];
#pragma unroll
            for (int c = 0; c < DH; c++) z += sWd[d * DH + c] * codes[c];
            out[i * DIN + d] = z;
        }
    }
    if (tid == 0) g_cnt[mt] = 0;   // self-reset for next graph replay
}

// ---------------- launch ----------------
extern "C" void kernel_launch(void* const* d_in, const int* in_sizes, int n_in,
                              void* d_out, int out_size)
{
    const float* x  = (const float*)d_in[0];
    const float* W1 = (const float*)d_in[1];
    const float* b1 = (const float*)d_in[2];
    const float* W2 = (const float*)d_in[3];
    const float* b2 = (const float*)d_in[4];
    const float* W3 = (const float*)d_in[5];
    const float* b3 = (const float*)d_in[6];
    const float* We = (const float*)d_in[7];
    const float* be = (const float*)d_in[8];
    const float* Wd = (const float*)d_in[9];
    const float* bd = (const float*)d_in[10];
    float* out = (float*)d_out;

    prep_kernel<<<NN / 32, 32>>>(x, W1, b1, W2, b2, W3, b3);
    dim3 grid(KC, MT);
    pairmma_kernel<<<grid, 128>>>(x, We, be, Wd, bd, out);
}